// round 9
// baseline (speedup 1.0000x reference)
#include <cuda_runtime.h>
#include <cuda_bf16.h>
#include <cstdint>
#include <math.h>

#define N_NODES 10000
#define N_EDGES 160000
#define F_DIM 4
#define T_DIM 12
#define C_DIM 512
#define HID_DIM 256
#define OUT_DIM 12
#define FT (F_DIM * T_DIM)
#define KPAIRS 256          // 512 k values -> 256 u32 bf16 pairs per row

// ---------------- scratch (__device__ globals; no allocations allowed) ----------------
__device__ float g_deg[N_NODES];
__device__ float g_dinv[N_NODES];
__device__ float g_agg[(size_t)N_NODES * FT];
__device__ float g_U[3 * F_DIM * C_DIM];
__device__ float g_beff[3 * C_DIM];
__device__ float g_Uzr[F_DIM * 2 * C_DIM];
__device__ float g_beffzr[2 * C_DIM];
__device__ float g_probs[T_DIM];
__device__ float g_H[2][(size_t)N_NODES * C_DIM];     // fp32 H (epilogue reads)
__device__ float g_z[(size_t)N_NODES * C_DIM];
__device__ float g_Hacc[(size_t)N_NODES * C_DIM];
__device__ float g_h1[(size_t)N_NODES * HID_DIM];
// bf16 hi/lo packed planes (A operands), [node][256] u32
__device__ uint32_t g_Hpl[2][2][(size_t)N_NODES * KPAIRS];   // [buf][hi=0/lo=1]
__device__ uint32_t g_Hrpl[2][(size_t)N_NODES * KPAIRS];     // Hr planes
__device__ uint32_t g_HApl[2][(size_t)N_NODES * KPAIRS];     // relu(Hacc) planes
// transposed + bf16-split pair-packed weights
#define BT_ZR_OFF 0
#define BT_H_OFF  (1024 * 256)
#define BT_1_OFF  (1024 * 256 + 512 * 256)
#define BT_PAIRS  ((1024 + 512 + 256) * 256)
__device__ uint32_t g_Bthi[BT_PAIRS];
__device__ uint32_t g_Btlo[BT_PAIRS];

// ---------------- helpers ----------------
__device__ __forceinline__ uint32_t pack_bf16x2(float a, float b) {
    uint32_t r;
    asm("cvt.rn.bf16x2.f32 %0, %1, %2;" : "=r"(r) : "f"(b), "f"(a));
    return r;
}
__device__ __forceinline__ void split2_store(float v0, float v1,
                                             uint32_t* hip, uint32_t* lop) {
    float h0 = __bfloat162float(__float2bfloat16_rn(v0));
    float h1 = __bfloat162float(__float2bfloat16_rn(v1));
    *hip = pack_bf16x2(v0, v1);
    *lop = pack_bf16x2(v0 - h0, v1 - h1);
}
__device__ __forceinline__ void mma_bf16(float* c, const uint32_t* a, const uint32_t* b) {
    asm volatile(
        "mma.sync.aligned.m16n8k16.row.col.f32.bf16.bf16.f32 "
        "{%0,%1,%2,%3}, {%4,%5,%6,%7}, {%8,%9}, {%0,%1,%2,%3};"
        : "+f"(c[0]), "+f"(c[1]), "+f"(c[2]), "+f"(c[3])
        : "r"(a[0]), "r"(a[1]), "r"(a[2]), "r"(a[3]), "r"(b[0]), "r"(b[1]));
}
#define LDMX4(r0, r1, r2, r3, addr) \
    asm volatile("ldmatrix.sync.aligned.m8n8.x4.shared.b16 {%0,%1,%2,%3}, [%4];" \
        : "=r"(r0), "=r"(r1), "=r"(r2), "=r"(r3) : "r"(addr))

// ---------------- small setup kernels ----------------
__global__ void init_state(float* H0, float* Hacc, float* deg,
                           uint32_t* Hpl_hi, uint32_t* Hpl_lo) {
    int idx = blockIdx.x * blockDim.x + threadIdx.x;
    if (idx < N_NODES * C_DIM) { H0[idx] = 0.f; Hacc[idx] = 0.f; }
    if (idx < N_NODES * KPAIRS) { Hpl_hi[idx] = 0u; Hpl_lo[idx] = 0u; }
    if (idx < N_NODES) deg[idx] = 1.f;
}
__global__ void deg_scatter(const int* __restrict__ ei, const float* __restrict__ ea,
                            float* __restrict__ deg) {
    int e = blockIdx.x * blockDim.x + threadIdx.x;
    if (e >= N_EDGES) return;
    atomicAdd(&deg[ei[N_EDGES + e]], ea[e]);
}
__global__ void compute_dinv(const float* __restrict__ deg, float* __restrict__ dinv) {
    int i = blockIdx.x * blockDim.x + threadIdx.x;
    if (i >= N_NODES) return;
    dinv[i] = rsqrtf(fmaxf(deg[i], 1e-12f));
}
__global__ void agg_init(const float* __restrict__ x, const float* __restrict__ dinv,
                         float* __restrict__ agg) {
    int idx = blockIdx.x * blockDim.x + threadIdx.x;
    if (idx >= N_NODES * FT) return;
    int i = idx / FT;
    float d = dinv[i];
    agg[idx] = d * d * x[idx];
}
__global__ void agg_scatter(const float* __restrict__ x, const int* __restrict__ ei,
                            const float* __restrict__ ea, const float* __restrict__ dinv,
                            float* __restrict__ agg) {
    long long idx = (long long)blockIdx.x * blockDim.x + threadIdx.x;
    if (idx >= (long long)N_EDGES * FT) return;
    int e = (int)(idx / FT);
    int k = (int)(idx % FT);
    int s = ei[e];
    int d = ei[N_EDGES + e];
    float coef = dinv[s] * ea[e] * dinv[d];
    atomicAdd(&agg[(size_t)d * FT + k], coef * x[(size_t)s * FT + k]);
}
__global__ void softmax12(const float* __restrict__ att, float* __restrict__ probs) {
    if (threadIdx.x == 0) {
        float m = -1e30f;
        for (int i = 0; i < T_DIM; i++) m = fmaxf(m, att[i]);
        float e[T_DIM]; float s = 0.f;
        for (int i = 0; i < T_DIM; i++) { e[i] = expf(att[i] - m); s += e[i]; }
        float inv = 1.f / s;
        for (int i = 0; i < T_DIM; i++) probs[i] = e[i] * inv;
    }
}
__global__ void compute_U(const float* Wzg, const float* Wrg, const float* Whg,
                          const float* Wzl, const float* Wrl, const float* Whl,
                          float* U) {
    int idx = blockIdx.x * blockDim.x + threadIdx.x;
    if (idx >= 3 * F_DIM * C_DIM) return;
    int g = idx / (F_DIM * C_DIM);
    int rem = idx % (F_DIM * C_DIM);
    int f = rem / C_DIM;
    int c = rem % C_DIM;
    const float* Wg = (g == 0) ? Wzg : (g == 1) ? Wrg : Whg;
    const float* Wl = (g == 0) ? Wzl : (g == 1) ? Wrl : Whl;
    float s = 0.f;
    for (int k = 0; k < C_DIM; k++) s += Wg[f * C_DIM + k] * Wl[(size_t)k * C_DIM + c];
    U[idx] = s;
}
__global__ void compute_beff(const float* bzg, const float* brg, const float* bhg,
                             const float* Wzl, const float* Wrl, const float* Whl,
                             const float* bzl, const float* brl, const float* bhl,
                             float* beff) {
    int idx = blockIdx.x * blockDim.x + threadIdx.x;
    if (idx >= 3 * C_DIM) return;
    int g = idx / C_DIM;
    int c = idx % C_DIM;
    const float* bg = (g == 0) ? bzg : (g == 1) ? brg : bhg;
    const float* Wl = (g == 0) ? Wzl : (g == 1) ? Wrl : Whl;
    const float* bl = (g == 0) ? bzl : (g == 1) ? brl : bhl;
    float s = bl[c];
    for (int k = 0; k < C_DIM; k++) s += bg[k] * Wl[(size_t)k * C_DIM + c];
    beff[idx] = s;
}
__global__ void pack_zr(const float* __restrict__ U, const float* __restrict__ beff,
                        float* __restrict__ Uzr, float* __restrict__ beffzr) {
    int idx = blockIdx.x * blockDim.x + threadIdx.x;
    if (idx < F_DIM * 1024) {
        int f = idx >> 10;
        int c = idx & 1023;
        int gt = (c >> 9);
        Uzr[idx] = U[gt * (F_DIM * C_DIM) + f * C_DIM + (c & 511)];
    }
    if (idx < 1024) {
        int gt = idx >> 9;
        beffzr[idx] = beff[gt * C_DIM + (idx & 511)];
    }
}
__global__ void transpose_split_B(const float* Wzl, const float* Wrl, const float* Whl,
                                  const float* W1,
                                  uint32_t* __restrict__ Bthi, uint32_t* __restrict__ Btlo) {
    int idx = blockIdx.x * blockDim.x + threadIdx.x;
    if (idx >= BT_PAIRS) return;
    const int ZR = 1024 * 256, HH = 512 * 256;
    float v0, v1;
    if (idx < ZR) {
        int n = idx >> 8, pk = idx & 255;
        int k0 = pk * 2;
        if (n < 512) {
            v0 = Wzl[(size_t)(C_DIM + k0) * C_DIM + n];
            v1 = Wzl[(size_t)(C_DIM + k0 + 1) * C_DIM + n];
        } else {
            v0 = Wrl[(size_t)(C_DIM + k0) * C_DIM + (n - 512)];
            v1 = Wrl[(size_t)(C_DIM + k0 + 1) * C_DIM + (n - 512)];
        }
    } else if (idx < ZR + HH) {
        int r = idx - ZR;
        int n = r >> 8, pk = r & 255;
        int k0 = pk * 2;
        v0 = Whl[(size_t)(C_DIM + k0) * C_DIM + n];
        v1 = Whl[(size_t)(C_DIM + k0 + 1) * C_DIM + n];
    } else {
        int r = idx - ZR - HH;
        int n = r >> 8, pk = r & 255;
        int k0 = pk * 2;
        v0 = W1[(size_t)k0 * HID_DIM + n];
        v1 = W1[(size_t)(k0 + 1) * HID_DIM + n];
    }
    split2_store(v0, v1, &Bthi[idx], &Btlo[idx]);
}

// ---------------- 3x bf16 mma GEMM: A from packed planes, ldmatrix fragments ----------------
// mode 0 (zr): c<512 -> z=sigmoid(v) fp32;  c>=512 -> Hr=Hin*sigmoid(v) -> planes
// mode 2 (h):  Hn=z*Hin+(1-z)*tanh(v) -> fp32 + planes; Hacc += p*Hn; t==11: HA planes
// mode 3 (head): out0 = relu(v) fp32
#define BMT 128
#define BNT 128
#define SPAD 20   // u32 per smem row (16 data + 4 pad); 80B row stride, 16B-aligned

__global__ __launch_bounds__(256, 2) void gemm_bf16(
    const uint32_t* __restrict__ Ahi_g, const uint32_t* __restrict__ Alo_g,
    const uint32_t* __restrict__ Bthi, const uint32_t* __restrict__ Btlo,
    int M, int Nc, int mode, int t,
    const float* __restrict__ agg, const float* __restrict__ U, int ustride,
    const float* __restrict__ beff,
    const float* __restrict__ Hin, const float* __restrict__ Z,
    float* __restrict__ out0,
    uint32_t* __restrict__ pl_hi, uint32_t* __restrict__ pl_lo,
    float* __restrict__ Hacc,
    uint32_t* __restrict__ ha_hi, uint32_t* __restrict__ ha_lo,
    const float* __restrict__ probs)
{
    __shared__ uint32_t Ahi[BMT][SPAD];
    __shared__ uint32_t Alo[BMT][SPAD];
    __shared__ uint32_t Bhi[BNT][SPAD];
    __shared__ uint32_t Blo[BNT][SPAD];
    __shared__ float aggS[BMT][F_DIM];

    const int tid = threadIdx.x;
    const int wid = tid >> 5;
    const int lane = tid & 31;
    const int g8 = lane >> 2;
    const int tig = lane & 3;
    const int wm = wid >> 2;        // 0..1
    const int wn = wid & 3;         // 0..3
    const int row0 = blockIdx.y * BMT;
    const int col0 = blockIdx.x * BNT;

    if (mode != 3) {
        for (int i = tid; i < BMT * F_DIM; i += 256) {
            int r = i >> 2, f = i & 3;
            aggS[r][f] = (row0 + r < M) ? agg[(size_t)(row0 + r) * FT + f * T_DIM + t] : 0.f;
        }
    }

    // ldmatrix lane-derived base addresses (A fragment x4, B double-fragment x4)
    const int a_row = wm * 64 + ((lane >> 3) & 1) * 8 + (lane & 7);
    const int a_col = (lane >> 4) * 4;
    const int b_row = wn * 32 + (lane >> 4) * 8 + (lane & 7);
    const int b_col = ((lane >> 3) & 1) * 4;
    const uint32_t aHiA = (uint32_t)__cvta_generic_to_shared(&Ahi[a_row][a_col]);
    const uint32_t aLoA = (uint32_t)__cvta_generic_to_shared(&Alo[a_row][a_col]);
    const uint32_t bHiA = (uint32_t)__cvta_generic_to_shared(&Bhi[b_row][b_col]);
    const uint32_t bLoA = (uint32_t)__cvta_generic_to_shared(&Blo[b_row][b_col]);

    // tile-fill indices: 512 uint4 per plane, 2 per thread
    const int f_r = tid >> 1;            // 0..127
    const int f_q = (tid & 1) * 2;       // 0 or 2  (two uint4 slots: q, q+1)

    float acc[4][4][4];
#pragma unroll
    for (int a = 0; a < 4; a++)
#pragma unroll
        for (int b = 0; b < 4; b++)
#pragma unroll
            for (int c = 0; c < 4; c++) acc[a][b][c] = 0.f;

    for (int kc = 0; kc < 16; kc++) {
        // ---- fill A planes (pure LDG->STS) ----
        {
            int gr = row0 + f_r;
            uint4 h0 = make_uint4(0u, 0u, 0u, 0u), h1 = h0, l0 = h0, l1 = h0;
            if (gr < M) {
                size_t go = (size_t)gr * 64 + kc * 4 + f_q;
                h0 = ((const uint4*)Ahi_g)[go];
                h1 = ((const uint4*)Ahi_g)[go + 1];
                l0 = ((const uint4*)Alo_g)[go];
                l1 = ((const uint4*)Alo_g)[go + 1];
            }
            *(uint4*)&Ahi[f_r][f_q * 4]     = h0;
            *(uint4*)&Ahi[f_r][f_q * 4 + 4] = h1;
            *(uint4*)&Alo[f_r][f_q * 4]     = l0;
            *(uint4*)&Alo[f_r][f_q * 4 + 4] = l1;
        }
        // ---- fill B planes ----
        {
            size_t go = (size_t)(col0 + f_r) * 64 + kc * 4 + f_q;
            uint4 h0 = ((const uint4*)Bthi)[go];
            uint4 h1 = ((const uint4*)Bthi)[go + 1];
            uint4 l0 = ((const uint4*)Btlo)[go];
            uint4 l1 = ((const uint4*)Btlo)[go + 1];
            *(uint4*)&Bhi[f_r][f_q * 4]     = h0;
            *(uint4*)&Bhi[f_r][f_q * 4 + 4] = h1;
            *(uint4*)&Blo[f_r][f_q * 4]     = l0;
            *(uint4*)&Blo[f_r][f_q * 4 + 4] = l1;
        }
        __syncthreads();

#pragma unroll
        for (int kb = 0; kb < 2; kb++) {
            const uint32_t koff = kb * 32;   // 8 u32 = 32 bytes per k16 step
            uint32_t ah[4][4], al[4][4];
#pragma unroll
            for (int mt = 0; mt < 4; mt++) {
                const uint32_t moff = mt * (16 * SPAD * 4);
                LDMX4(ah[mt][0], ah[mt][1], ah[mt][2], ah[mt][3], aHiA + moff + koff);
                LDMX4(al[mt][0], al[mt][1], al[mt][2], al[mt][3], aLoA + moff + koff);
            }
            uint32_t bh[4][2], bl[4][2];
#pragma unroll
            for (int ntp = 0; ntp < 2; ntp++) {
                const uint32_t noff = ntp * (16 * SPAD * 4);
                LDMX4(bh[2 * ntp][0], bh[2 * ntp][1], bh[2 * ntp + 1][0], bh[2 * ntp + 1][1],
                      bHiA + noff + koff);
                LDMX4(bl[2 * ntp][0], bl[2 * ntp][1], bl[2 * ntp + 1][0], bl[2 * ntp + 1][1],
                      bLoA + noff + koff);
            }
#pragma unroll
            for (int mt = 0; mt < 4; mt++) {
#pragma unroll
                for (int nt = 0; nt < 4; nt++) mma_bf16(acc[mt][nt], ah[mt], bh[nt]);
#pragma unroll
                for (int nt = 0; nt < 4; nt++) mma_bf16(acc[mt][nt], ah[mt], bl[nt]);
#pragma unroll
                for (int nt = 0; nt < 4; nt++) mma_bf16(acc[mt][nt], al[mt], bh[nt]);
            }
        }
        __syncthreads();
    }

    // ---- fused epilogue ----
    const float p = (mode == 2) ? probs[t] : 0.f;
    const bool last_t = (mode == 2) && (t == T_DIM - 1);
#pragma unroll
    for (int mt = 0; mt < 4; mt++) {
#pragma unroll
        for (int i = 0; i < 2; i++) {
            int rl = wm * 64 + mt * 16 + g8 + i * 8;
            int gr = row0 + rl;
            if (gr >= M) continue;
            float a0 = 0.f, a1 = 0.f, a2 = 0.f, a3 = 0.f;
            if (mode != 3) {
                a0 = aggS[rl][0]; a1 = aggS[rl][1];
                a2 = aggS[rl][2]; a3 = aggS[rl][3];
            }
#pragma unroll
            for (int nt = 0; nt < 4; nt++) {
                const int cg0 = col0 + wn * 32 + nt * 8 + tig * 2;
                float vv[2];
#pragma unroll
                for (int jj = 0; jj < 2; jj++) {
                    int cg = cg0 + jj;
                    float v = acc[mt][nt][i * 2 + jj] + beff[cg];
                    if (mode != 3)
                        v += a0 * U[cg] + a1 * U[ustride + cg]
                           + a2 * U[2 * ustride + cg] + a3 * U[3 * ustride + cg];
                    vv[jj] = v;
                }
                if (mode == 0) {
                    if (cg0 < 512) {
                        out0[(size_t)gr * C_DIM + cg0]     = 1.f / (1.f + expf(-vv[0]));
                        out0[(size_t)gr * C_DIM + cg0 + 1] = 1.f / (1.f + expf(-vv[1]));
                    } else {
                        size_t o = (size_t)gr * C_DIM + (cg0 - 512);
                        float hr0 = Hin[o]     * (1.f / (1.f + expf(-vv[0])));
                        float hr1 = Hin[o + 1] * (1.f / (1.f + expf(-vv[1])));
                        size_t pp = (size_t)gr * KPAIRS + ((cg0 - 512) >> 1);
                        split2_store(hr0, hr1, &pl_hi[pp], &pl_lo[pp]);
                    }
                } else if (mode == 2) {
                    size_t o = (size_t)gr * C_DIM + cg0;
                    float z0 = Z[o], z1 = Z[o + 1];
                    float hn0 = z0 * Hin[o]     + (1.f - z0) * tanhf(vv[0]);
                    float hn1 = z1 * Hin[o + 1] + (1.f - z1) * tanhf(vv[1]);
                    out0[o]     = hn0;
                    out0[o + 1] = hn1;
                    size_t pp = (size_t)gr * KPAIRS + (cg0 >> 1);
                    split2_store(hn0, hn1, &pl_hi[pp], &pl_lo[pp]);
                    float ha0 = Hacc[o]     + p * hn0;
                    float ha1 = Hacc[o + 1] + p * hn1;
                    Hacc[o]     = ha0;
                    Hacc[o + 1] = ha1;
                    if (last_t)
                        split2_store(fmaxf(ha0, 0.f), fmaxf(ha1, 0.f), &ha_hi[pp], &ha_lo[pp]);
                } else {
                    out0[(size_t)gr * HID_DIM + cg0]     = fmaxf(vv[0], 0.f);
                    out0[(size_t)gr * HID_DIM + cg0 + 1] = fmaxf(vv[1], 0.f);
                }
            }
        }
    }
}

// out[i,j] = h1[i,:] @ W2[:,j] + b2[j]
__global__ void head2(const float* __restrict__ h1, const float* __restrict__ W2,
                      const float* __restrict__ b2, float* __restrict__ out) {
    int idx = blockIdx.x * blockDim.x + threadIdx.x;
    if (idx >= N_NODES * OUT_DIM) return;
    int i = idx / OUT_DIM;
    int j = idx % OUT_DIM;
    float s = b2[j];
    const float* hr = h1 + (size_t)i * HID_DIM;
    for (int k = 0; k < HID_DIM; k++) s += hr[k] * W2[k * OUT_DIM + j];
    out[idx] = s;
}
__global__ void copy_hidden(const float* __restrict__ Hacc, float* __restrict__ out) {
    int idx = blockIdx.x * blockDim.x + threadIdx.x;
    if (idx >= N_NODES * C_DIM) return;
    out[idx] = Hacc[idx];
}

// ---------------- host launcher ----------------
extern "C" void kernel_launch(void* const* d_in, const int* in_sizes, int n_in,
                              void* d_out, int out_size) {
    const float* x   = (const float*)d_in[0];
    const int*   ei  = (const int*)d_in[1];
    const float* ea  = (const float*)d_in[2];
    const float* att = (const float*)d_in[3];
    const float* Wg[3] = {(const float*)d_in[4],  (const float*)d_in[8],  (const float*)d_in[12]};
    const float* bg[3] = {(const float*)d_in[5],  (const float*)d_in[9],  (const float*)d_in[13]};
    const float* Wl[3] = {(const float*)d_in[6],  (const float*)d_in[10], (const float*)d_in[14]};
    const float* bl[3] = {(const float*)d_in[7],  (const float*)d_in[11], (const float*)d_in[15]};
    const float* W1 = (const float*)d_in[16];
    const float* b1 = (const float*)d_in[17];
    const float* W2 = (const float*)d_in[18];
    const float* b2 = (const float*)d_in[19];
    float* out = (float*)d_out;

    float *deg, *dinv, *agg, *U, *beff, *Uzr, *beffzr, *probs, *Hbase, *zb, *Hacc, *h1;
    uint32_t *Bthi, *Btlo, *Hpl, *Hrpl, *HApl;
    cudaGetSymbolAddress((void**)&deg,    g_deg);
    cudaGetSymbolAddress((void**)&dinv,   g_dinv);
    cudaGetSymbolAddress((void**)&agg,    g_agg);
    cudaGetSymbolAddress((void**)&U,      g_U);
    cudaGetSymbolAddress((void**)&beff,   g_beff);
    cudaGetSymbolAddress((void**)&Uzr,    g_Uzr);
    cudaGetSymbolAddress((void**)&beffzr, g_beffzr);
    cudaGetSymbolAddress((void**)&probs,  g_probs);
    cudaGetSymbolAddress((void**)&Hbase,  g_H);
    cudaGetSymbolAddress((void**)&zb,     g_z);
    cudaGetSymbolAddress((void**)&Hacc,   g_Hacc);
    cudaGetSymbolAddress((void**)&h1,     g_h1);
    cudaGetSymbolAddress((void**)&Bthi,   g_Bthi);
    cudaGetSymbolAddress((void**)&Btlo,   g_Btlo);
    cudaGetSymbolAddress((void**)&Hpl,    g_Hpl);
    cudaGetSymbolAddress((void**)&Hrpl,   g_Hrpl);
    cudaGetSymbolAddress((void**)&HApl,   g_HApl);
    float* H[2] = {Hbase, Hbase + (size_t)N_NODES * C_DIM};
    const size_t PL = (size_t)N_NODES * KPAIRS;
    uint32_t* Hpl_hi[2] = {Hpl,            Hpl + 2 * PL};
    uint32_t* Hpl_lo[2] = {Hpl + PL,       Hpl + 3 * PL};
    uint32_t* Hr_hi = Hrpl;
    uint32_t* Hr_lo = Hrpl + PL;
    uint32_t* HA_hi = HApl;
    uint32_t* HA_lo = HApl + PL;

    // setup
    init_state<<<(N_NODES * C_DIM + 255) / 256, 256>>>(H[0], Hacc, deg, Hpl_hi[0], Hpl_lo[0]);
    deg_scatter<<<(N_EDGES + 255) / 256, 256>>>(ei, ea, deg);
    compute_dinv<<<(N_NODES + 255) / 256, 256>>>(deg, dinv);
    agg_init<<<(N_NODES * FT + 255) / 256, 256>>>(x, dinv, agg);
    {
        long long tot = (long long)N_EDGES * FT;
        agg_scatter<<<(unsigned)((tot + 255) / 256), 256>>>(x, ei, ea, dinv, agg);
    }
    softmax12<<<1, 32>>>(att, probs);
    compute_U<<<(3 * F_DIM * C_DIM + 255) / 256, 256>>>(Wg[0], Wg[1], Wg[2], Wl[0], Wl[1], Wl[2], U);
    compute_beff<<<(3 * C_DIM + 255) / 256, 256>>>(bg[0], bg[1], bg[2], Wl[0], Wl[1], Wl[2],
                                                   bl[0], bl[1], bl[2], beff);
    pack_zr<<<(F_DIM * 1024 + 255) / 256, 256>>>(U, beff, Uzr, beffzr);
    transpose_split_B<<<(BT_PAIRS + 255) / 256, 256>>>(Wl[0], Wl[1], Wl[2], W1, Bthi, Btlo);

    dim3 blk(256);
    dim3 gridZR(1024 / BNT, (N_NODES + BMT - 1) / BMT);
    dim3 gridH(512 / BNT, (N_NODES + BMT - 1) / BMT);
    int hin = 0;
    for (int t = 0; t < T_DIM; t++) {
        // fused z+r: z -> zb (fp32), Hr -> planes
        gemm_bf16<<<gridZR, blk>>>(Hpl_hi[hin], Hpl_lo[hin],
                                   Bthi + BT_ZR_OFF, Btlo + BT_ZR_OFF,
                                   N_NODES, 1024, 0, t,
                                   agg, Uzr, 1024, beffzr,
                                   H[hin], nullptr, zb,
                                   Hr_hi, Hr_lo, nullptr, nullptr, nullptr, probs);
        // h gate: Hn fp32+planes; Hacc += p*Hn; (t==11: HA planes)
        gemm_bf16<<<gridH, blk>>>(Hr_hi, Hr_lo,
                                  Bthi + BT_H_OFF, Btlo + BT_H_OFF,
                                  N_NODES, 512, 2, t,
                                  agg, U + 2 * F_DIM * C_DIM, 512, beff + 2 * C_DIM,
                                  H[hin], zb, H[1 - hin],
                                  Hpl_hi[1 - hin], Hpl_lo[1 - hin],
                                  Hacc, HA_hi, HA_lo, probs);
        hin ^= 1;
    }

    // head: h1 = relu(relu(Hacc) @ W1 + b1), A = HA planes (already relu'd)
    dim3 gridHead(HID_DIM / BNT, (N_NODES + BMT - 1) / BMT);
    gemm_bf16<<<gridHead, blk>>>(HA_hi, HA_lo,
                                 Bthi + BT_1_OFF, Btlo + BT_1_OFF,
                                 N_NODES, HID_DIM, 3, 0,
                                 nullptr, nullptr, 0, b1,
                                 nullptr, nullptr, h1,
                                 nullptr, nullptr, nullptr, nullptr, nullptr, probs);
    head2<<<(N_NODES * OUT_DIM + 255) / 256, 256>>>(h1, W2, b2, out);
    copy_hidden<<<(N_NODES * C_DIM + 255) / 256, 256>>>(Hacc, out + (size_t)N_NODES * OUT_DIM);
}

// round 11
// speedup vs baseline: 1.1063x; 1.1063x over previous
#include <cuda_runtime.h>
#include <cuda_bf16.h>
#include <cstdint>
#include <math.h>

#define N_NODES 10000
#define N_EDGES 160000
#define F_DIM 4
#define T_DIM 12
#define C_DIM 512
#define HID_DIM 256
#define OUT_DIM 12
#define FT (F_DIM * T_DIM)
#define KPAIRS 256          // 512 k values -> 256 u32 bf16 pairs per row

// ---------------- scratch (__device__ globals; no allocations allowed) ----------------
__device__ float g_deg[N_NODES];
__device__ float g_dinv[N_NODES];
__device__ float g_agg[(size_t)N_NODES * FT];
__device__ float g_U[3 * F_DIM * C_DIM];
__device__ float g_beff[3 * C_DIM];
__device__ float g_Uzr[F_DIM * 2 * C_DIM];
__device__ float g_beffzr[2 * C_DIM];
__device__ float g_probs[T_DIM];
__device__ float g_H[2][(size_t)N_NODES * C_DIM];
__device__ float g_z[(size_t)N_NODES * C_DIM];
__device__ float g_Hacc[(size_t)N_NODES * C_DIM];
__device__ float g_h1[(size_t)N_NODES * HID_DIM];
// bf16 hi/lo packed planes (A operands), [node][256] u32
__device__ uint32_t g_Hpl[2][2][(size_t)N_NODES * KPAIRS];   // [buf][hi/lo]
__device__ uint32_t g_Hrpl[2][(size_t)N_NODES * KPAIRS];
__device__ uint32_t g_HApl[2][(size_t)N_NODES * KPAIRS];
// transposed + bf16-split pair-packed weights
#define BT_ZR_OFF 0
#define BT_H_OFF  (1024 * 256)
#define BT_1_OFF  (1024 * 256 + 512 * 256)
#define BT_PAIRS  ((1024 + 512 + 256) * 256)
__device__ uint32_t g_Bthi[BT_PAIRS];
__device__ uint32_t g_Btlo[BT_PAIRS];

// ---------------- helpers ----------------
__device__ __forceinline__ uint32_t pack_bf16x2(float a, float b) {
    uint32_t r;
    asm("cvt.rn.bf16x2.f32 %0, %1, %2;" : "=r"(r) : "f"(b), "f"(a));
    return r;
}
__device__ __forceinline__ void split2_store(float v0, float v1,
                                             uint32_t* hip, uint32_t* lop) {
    float h0 = __bfloat162float(__float2bfloat16_rn(v0));
    float h1 = __bfloat162float(__float2bfloat16_rn(v1));
    *hip = pack_bf16x2(v0, v1);
    *lop = pack_bf16x2(v0 - h0, v1 - h1);
}
__device__ __forceinline__ void mma_bf16(float* c, const uint32_t* a, const uint32_t* b) {
    asm volatile(
        "mma.sync.aligned.m16n8k16.row.col.f32.bf16.bf16.f32 "
        "{%0,%1,%2,%3}, {%4,%5,%6,%7}, {%8,%9}, {%0,%1,%2,%3};"
        : "+f"(c[0]), "+f"(c[1]), "+f"(c[2]), "+f"(c[3])
        : "r"(a[0]), "r"(a[1]), "r"(a[2]), "r"(a[3]), "r"(b[0]), "r"(b[1]));
}
#define CP_ASYNC16(dst, src, sz) \
    asm volatile("cp.async.cg.shared.global [%0], [%1], 16, %2;" \
        :: "r"(dst), "l"(src), "r"(sz) : "memory")
#define CP_COMMIT() asm volatile("cp.async.commit_group;" ::: "memory")
#define CP_WAIT(n)  asm volatile("cp.async.wait_group %0;" :: "n"(n) : "memory")

// ---------------- small setup kernels ----------------
__global__ void init_state(float* H0, float* Hacc, float* deg,
                           uint32_t* Hpl_hi, uint32_t* Hpl_lo) {
    int idx = blockIdx.x * blockDim.x + threadIdx.x;
    if (idx < N_NODES * C_DIM) { H0[idx] = 0.f; Hacc[idx] = 0.f; }
    if (idx < N_NODES * KPAIRS) { Hpl_hi[idx] = 0u; Hpl_lo[idx] = 0u; }
    if (idx < N_NODES) deg[idx] = 1.f;
}
__global__ void deg_scatter(const int* __restrict__ ei, const float* __restrict__ ea,
                            float* __restrict__ deg) {
    int e = blockIdx.x * blockDim.x + threadIdx.x;
    if (e >= N_EDGES) return;
    atomicAdd(&deg[ei[N_EDGES + e]], ea[e]);
}
__global__ void compute_dinv(const float* __restrict__ deg, float* __restrict__ dinv) {
    int i = blockIdx.x * blockDim.x + threadIdx.x;
    if (i >= N_NODES) return;
    dinv[i] = rsqrtf(fmaxf(deg[i], 1e-12f));
}
__global__ void agg_init(const float* __restrict__ x, const float* __restrict__ dinv,
                         float* __restrict__ agg) {
    int idx = blockIdx.x * blockDim.x + threadIdx.x;
    if (idx >= N_NODES * FT) return;
    int i = idx / FT;
    float d = dinv[i];
    agg[idx] = d * d * x[idx];
}
__global__ void agg_scatter(const float* __restrict__ x, const int* __restrict__ ei,
                            const float* __restrict__ ea, const float* __restrict__ dinv,
                            float* __restrict__ agg) {
    long long idx = (long long)blockIdx.x * blockDim.x + threadIdx.x;
    if (idx >= (long long)N_EDGES * FT) return;
    int e = (int)(idx / FT);
    int k = (int)(idx % FT);
    int s = ei[e];
    int d = ei[N_EDGES + e];
    float coef = dinv[s] * ea[e] * dinv[d];
    atomicAdd(&agg[(size_t)d * FT + k], coef * x[(size_t)s * FT + k]);
}
__global__ void softmax12(const float* __restrict__ att, float* __restrict__ probs) {
    if (threadIdx.x == 0) {
        float m = -1e30f;
        for (int i = 0; i < T_DIM; i++) m = fmaxf(m, att[i]);
        float e[T_DIM]; float s = 0.f;
        for (int i = 0; i < T_DIM; i++) { e[i] = expf(att[i] - m); s += e[i]; }
        float inv = 1.f / s;
        for (int i = 0; i < T_DIM; i++) probs[i] = e[i] * inv;
    }
}
__global__ void compute_U(const float* Wzg, const float* Wrg, const float* Whg,
                          const float* Wzl, const float* Wrl, const float* Whl,
                          float* U) {
    int idx = blockIdx.x * blockDim.x + threadIdx.x;
    if (idx >= 3 * F_DIM * C_DIM) return;
    int g = idx / (F_DIM * C_DIM);
    int rem = idx % (F_DIM * C_DIM);
    int f = rem / C_DIM;
    int c = rem % C_DIM;
    const float* Wg = (g == 0) ? Wzg : (g == 1) ? Wrg : Whg;
    const float* Wl = (g == 0) ? Wzl : (g == 1) ? Wrl : Whl;
    float s = 0.f;
    for (int k = 0; k < C_DIM; k++) s += Wg[f * C_DIM + k] * Wl[(size_t)k * C_DIM + c];
    U[idx] = s;
}
__global__ void compute_beff(const float* bzg, const float* brg, const float* bhg,
                             const float* Wzl, const float* Wrl, const float* Whl,
                             const float* bzl, const float* brl, const float* bhl,
                             float* beff) {
    int idx = blockIdx.x * blockDim.x + threadIdx.x;
    if (idx >= 3 * C_DIM) return;
    int g = idx / C_DIM;
    int c = idx % C_DIM;
    const float* bg = (g == 0) ? bzg : (g == 1) ? brg : bhg;
    const float* Wl = (g == 0) ? Wzl : (g == 1) ? Wrl : Whl;
    const float* bl = (g == 0) ? bzl : (g == 1) ? brl : bhl;
    float s = bl[c];
    for (int k = 0; k < C_DIM; k++) s += bg[k] * Wl[(size_t)k * C_DIM + c];
    beff[idx] = s;
}
__global__ void pack_zr(const float* __restrict__ U, const float* __restrict__ beff,
                        float* __restrict__ Uzr, float* __restrict__ beffzr) {
    int idx = blockIdx.x * blockDim.x + threadIdx.x;
    if (idx < F_DIM * 1024) {
        int f = idx >> 10;
        int c = idx & 1023;
        int gt = (c >> 9);
        Uzr[idx] = U[gt * (F_DIM * C_DIM) + f * C_DIM + (c & 511)];
    }
    if (idx < 1024) {
        int gt = idx >> 9;
        beffzr[idx] = beff[gt * C_DIM + (idx & 511)];
    }
}
__global__ void transpose_split_B(const float* Wzl, const float* Wrl, const float* Whl,
                                  const float* W1,
                                  uint32_t* __restrict__ Bthi, uint32_t* __restrict__ Btlo) {
    int idx = blockIdx.x * blockDim.x + threadIdx.x;
    if (idx >= BT_PAIRS) return;
    const int ZR = 1024 * 256, HH = 512 * 256;
    float v0, v1;
    if (idx < ZR) {
        int n = idx >> 8, pk = idx & 255;
        int k0 = pk * 2;
        if (n < 512) {
            v0 = Wzl[(size_t)(C_DIM + k0) * C_DIM + n];
            v1 = Wzl[(size_t)(C_DIM + k0 + 1) * C_DIM + n];
        } else {
            v0 = Wrl[(size_t)(C_DIM + k0) * C_DIM + (n - 512)];
            v1 = Wrl[(size_t)(C_DIM + k0 + 1) * C_DIM + (n - 512)];
        }
    } else if (idx < ZR + HH) {
        int r = idx - ZR;
        int n = r >> 8, pk = r & 255;
        int k0 = pk * 2;
        v0 = Whl[(size_t)(C_DIM + k0) * C_DIM + n];
        v1 = Whl[(size_t)(C_DIM + k0 + 1) * C_DIM + n];
    } else {
        int r = idx - ZR - HH;
        int n = r >> 8, pk = r & 255;
        int k0 = pk * 2;
        v0 = W1[(size_t)k0 * HID_DIM + n];
        v1 = W1[(size_t)(k0 + 1) * HID_DIM + n];
    }
    split2_store(v0, v1, &Bthi[idx], &Btlo[idx]);
}

// ---------------- bf16 mma GEMM: planes + cp.async double buffer, round-5 inner loop ----------------
// mode 0 (zr): c<512 -> z=sigmoid(v) fp32;  c>=512 -> Hr=Hin*sigmoid(v) -> planes
// mode 2 (h):  Hn=z*Hin+(1-z)*tanh(v) -> fp32 + planes; Hacc += p*Hn; t==11: HA planes
// mode 3 (head): out0 = relu(v) fp32
#define BMT 128
#define BNT 128
#define SPAD 20                      // u32 per smem row (16 data + 4 pad)
#define PLANE_U32 (BMT * SPAD)       // 2560
#define BUF_U32   (4 * PLANE_U32)    // 10240 (Ahi,Alo,Bhi,Blo)
#define SMEM_U32  (2 * BUF_U32 + BMT * F_DIM)
#define SMEM_BYTES (SMEM_U32 * 4)    // 83968

__global__ __launch_bounds__(256, 2) void gemm_bf16(
    const uint32_t* __restrict__ Ahi_g, const uint32_t* __restrict__ Alo_g,
    const uint32_t* __restrict__ Bthi, const uint32_t* __restrict__ Btlo,
    int M, int Nc, int mode, int t,
    const float* __restrict__ agg, const float* __restrict__ U, int ustride,
    const float* __restrict__ beff,
    const float* __restrict__ Hin, const float* __restrict__ Z,
    float* __restrict__ out0,
    uint32_t* __restrict__ pl_hi, uint32_t* __restrict__ pl_lo,
    float* __restrict__ Hacc,
    uint32_t* __restrict__ ha_hi, uint32_t* __restrict__ ha_lo,
    const float* __restrict__ probs)
{
    extern __shared__ uint32_t smem[];
    float* aggS = (float*)(smem + 2 * BUF_U32);

    const int tid = threadIdx.x;
    const int wid = tid >> 5;
    const int lane = tid & 31;
    const int g8 = lane >> 2;
    const int tig = lane & 3;
    const int wm = wid >> 2;        // 0..1
    const int wn = wid & 3;         // 0..3
    const int row0 = blockIdx.y * BMT;
    const int col0 = blockIdx.x * BNT;

    if (mode != 3) {
        for (int i = tid; i < BMT * F_DIM; i += 256) {
            int r = i >> 2, f = i & 3;
            aggS[i] = (row0 + r < M) ? agg[(size_t)(row0 + r) * FT + f * T_DIM + t] : 0.f;
        }
    }

    // fill indices: per plane 512 uint4; 2 per thread
    const int f_r = tid >> 1;            // 0..127
    const int f_q = (tid & 1) * 2;       // uint4 slots f_q, f_q+1
    const int a_gr = row0 + f_r;
    const uint32_t a_sz = (a_gr < M) ? 16u : 0u;
    const uint4* Ag_hi = (const uint4*)Ahi_g + (size_t)a_gr * 64 + f_q;
    const uint4* Ag_lo = (const uint4*)Alo_g + (size_t)a_gr * 64 + f_q;
    const uint4* Bg_hi = (const uint4*)Bthi + (size_t)(col0 + f_r) * 64 + f_q;
    const uint4* Bg_lo = (const uint4*)Btlo + (size_t)(col0 + f_r) * 64 + f_q;
    const uint32_t smem_fill0 =
        (uint32_t)__cvta_generic_to_shared(smem + f_r * SPAD + f_q * 4);

#define FILL_CHUNK(kc_, buf_) do {                                          \
        int _k4 = (kc_) * 4;                                                \
        uint32_t _d = smem_fill0 + (buf_) * (BUF_U32 * 4);                  \
        CP_ASYNC16(_d,                  Ag_hi + _k4,     a_sz);             \
        CP_ASYNC16(_d + 16,             Ag_hi + _k4 + 1, a_sz);             \
        CP_ASYNC16(_d + PLANE_U32*4,      Ag_lo + _k4,     a_sz);           \
        CP_ASYNC16(_d + PLANE_U32*4 + 16, Ag_lo + _k4 + 1, a_sz);           \
        CP_ASYNC16(_d + 2*PLANE_U32*4,      Bg_hi + _k4,     16u);          \
        CP_ASYNC16(_d + 2*PLANE_U32*4 + 16, Bg_hi + _k4 + 1, 16u);          \
        CP_ASYNC16(_d + 3*PLANE_U32*4,      Bg_lo + _k4,     16u);          \
        CP_ASYNC16(_d + 3*PLANE_U32*4 + 16, Bg_lo + _k4 + 1, 16u);          \
        CP_COMMIT();                                                        \
    } while (0)

    float acc[4][4][4];
#pragma unroll
    for (int a = 0; a < 4; a++)
#pragma unroll
        for (int b = 0; b < 4; b++)
#pragma unroll
            for (int c = 0; c < 4; c++) acc[a][b][c] = 0.f;

    FILL_CHUNK(0, 0);

    for (int kc = 0; kc < 16; kc++) {
        if (kc < 15) {
            FILL_CHUNK(kc + 1, (kc + 1) & 1);
            CP_WAIT(1);
        } else {
            CP_WAIT(0);
        }
        __syncthreads();

        const uint32_t* Ah = smem + (kc & 1) * BUF_U32;
        const uint32_t* Al = Ah + PLANE_U32;
        const uint32_t* Bh = Ah + 2 * PLANE_U32;
        const uint32_t* Bl = Ah + 3 * PLANE_U32;

#pragma unroll
        for (int kb = 0; kb < 2; kb++) {
            const int ko = kb * 8;
            uint32_t bh[4][2], bl[4][2];
#pragma unroll
            for (int nt = 0; nt < 4; nt++) {
                int n = wn * 32 + nt * 8 + g8;
                bh[nt][0] = Bh[n * SPAD + ko + tig];
                bh[nt][1] = Bh[n * SPAD + ko + tig + 4];
                bl[nt][0] = Bl[n * SPAD + ko + tig];
                bl[nt][1] = Bl[n * SPAD + ko + tig + 4];
            }
#pragma unroll
            for (int mt = 0; mt < 4; mt++) {
                int r = wm * 64 + mt * 16 + g8;
                uint32_t ah[4], al[4];
                ah[0] = Ah[r * SPAD + ko + tig];
                ah[1] = Ah[(r + 8) * SPAD + ko + tig];
                ah[2] = Ah[r * SPAD + ko + tig + 4];
                ah[3] = Ah[(r + 8) * SPAD + ko + tig + 4];
                al[0] = Al[r * SPAD + ko + tig];
                al[1] = Al[(r + 8) * SPAD + ko + tig];
                al[2] = Al[r * SPAD + ko + tig + 4];
                al[3] = Al[(r + 8) * SPAD + ko + tig + 4];
#pragma unroll
                for (int nt = 0; nt < 4; nt++) mma_bf16(acc[mt][nt], ah, bh[nt]);
#pragma unroll
                for (int nt = 0; nt < 4; nt++) mma_bf16(acc[mt][nt], ah, bl[nt]);
#pragma unroll
                for (int nt = 0; nt < 4; nt++) mma_bf16(acc[mt][nt], al, bh[nt]);
            }
        }
        __syncthreads();
    }

    // ---- fused epilogue ----
    const float p = (mode == 2) ? probs[t] : 0.f;
    const bool last_t = (mode == 2) && (t == T_DIM - 1);
#pragma unroll
    for (int mt = 0; mt < 4; mt++) {
#pragma unroll
        for (int i = 0; i < 2; i++) {
            int rl = wm * 64 + mt * 16 + g8 + i * 8;
            int gr = row0 + rl;
            if (gr >= M) continue;
            float a0 = 0.f, a1 = 0.f, a2 = 0.f, a3 = 0.f;
            if (mode != 3) {
                a0 = aggS[rl * 4 + 0]; a1 = aggS[rl * 4 + 1];
                a2 = aggS[rl * 4 + 2]; a3 = aggS[rl * 4 + 3];
            }
#pragma unroll
            for (int nt = 0; nt < 4; nt++) {
                const int cg0 = col0 + wn * 32 + nt * 8 + tig * 2;
                float vv[2];
#pragma unroll
                for (int jj = 0; jj < 2; jj++) {
                    int cg = cg0 + jj;
                    float v = acc[mt][nt][i * 2 + jj] + beff[cg];
                    if (mode != 3)
                        v += a0 * U[cg] + a1 * U[ustride + cg]
                           + a2 * U[2 * ustride + cg] + a3 * U[3 * ustride + cg];
                    vv[jj] = v;
                }
                if (mode == 0) {
                    if (cg0 < 512) {
                        out0[(size_t)gr * C_DIM + cg0]     = 1.f / (1.f + expf(-vv[0]));
                        out0[(size_t)gr * C_DIM + cg0 + 1] = 1.f / (1.f + expf(-vv[1]));
                    } else {
                        size_t o = (size_t)gr * C_DIM + (cg0 - 512);
                        float hr0 = Hin[o]     * (1.f / (1.f + expf(-vv[0])));
                        float hr1 = Hin[o + 1] * (1.f / (1.f + expf(-vv[1])));
                        size_t pp = (size_t)gr * KPAIRS + ((cg0 - 512) >> 1);
                        split2_store(hr0, hr1, &pl_hi[pp], &pl_lo[pp]);
                    }
                } else if (mode == 2) {
                    size_t o = (size_t)gr * C_DIM + cg0;
                    float z0 = Z[o], z1 = Z[o + 1];
                    float hn0 = z0 * Hin[o]     + (1.f - z0) * tanhf(vv[0]);
                    float hn1 = z1 * Hin[o + 1] + (1.f - z1) * tanhf(vv[1]);
                    out0[o]     = hn0;
                    out0[o + 1] = hn1;
                    size_t pp = (size_t)gr * KPAIRS + (cg0 >> 1);
                    split2_store(hn0, hn1, &pl_hi[pp], &pl_lo[pp]);
                    float ha0 = Hacc[o]     + p * hn0;
                    float ha1 = Hacc[o + 1] + p * hn1;
                    Hacc[o]     = ha0;
                    Hacc[o + 1] = ha1;
                    if (last_t)
                        split2_store(fmaxf(ha0, 0.f), fmaxf(ha1, 0.f), &ha_hi[pp], &ha_lo[pp]);
                } else {
                    out0[(size_t)gr * HID_DIM + cg0]     = fmaxf(vv[0], 0.f);
                    out0[(size_t)gr * HID_DIM + cg0 + 1] = fmaxf(vv[1], 0.f);
                }
            }
        }
    }
}

// out[i,j] = h1[i,:] @ W2[:,j] + b2[j]
__global__ void head2(const float* __restrict__ h1, const float* __restrict__ W2,
                      const float* __restrict__ b2, float* __restrict__ out) {
    int idx = blockIdx.x * blockDim.x + threadIdx.x;
    if (idx >= N_NODES * OUT_DIM) return;
    int i = idx / OUT_DIM;
    int j = idx % OUT_DIM;
    float s = b2[j];
    const float* hr = h1 + (size_t)i * HID_DIM;
    for (int k = 0; k < HID_DIM; k++) s += hr[k] * W2[k * OUT_DIM + j];
    out[idx] = s;
}
__global__ void copy_hidden(const float* __restrict__ Hacc, float* __restrict__ out) {
    int idx = blockIdx.x * blockDim.x + threadIdx.x;
    if (idx >= N_NODES * C_DIM) return;
    out[idx] = Hacc[idx];
}

// ---------------- host launcher ----------------
extern "C" void kernel_launch(void* const* d_in, const int* in_sizes, int n_in,
                              void* d_out, int out_size) {
    const float* x   = (const float*)d_in[0];
    const int*   ei  = (const int*)d_in[1];
    const float* ea  = (const float*)d_in[2];
    const float* att = (const float*)d_in[3];
    const float* Wg[3] = {(const float*)d_in[4],  (const float*)d_in[8],  (const float*)d_in[12]};
    const float* bg[3] = {(const float*)d_in[5],  (const float*)d_in[9],  (const float*)d_in[13]};
    const float* Wl[3] = {(const float*)d_in[6],  (const float*)d_in[10], (const float*)d_in[14]};
    const float* bl[3] = {(const float*)d_in[7],  (const float*)d_in[11], (const float*)d_in[15]};
    const float* W1 = (const float*)d_in[16];
    const float* b1 = (const float*)d_in[17];
    const float* W2 = (const float*)d_in[18];
    const float* b2 = (const float*)d_in[19];
    float* out = (float*)d_out;

    float *deg, *dinv, *agg, *U, *beff, *Uzr, *beffzr, *probs, *Hbase, *zb, *Hacc, *h1;
    uint32_t *Bthi, *Btlo, *Hpl, *Hrpl, *HApl;
    cudaGetSymbolAddress((void**)&deg,    g_deg);
    cudaGetSymbolAddress((void**)&dinv,   g_dinv);
    cudaGetSymbolAddress((void**)&agg,    g_agg);
    cudaGetSymbolAddress((void**)&U,      g_U);
    cudaGetSymbolAddress((void**)&beff,   g_beff);
    cudaGetSymbolAddress((void**)&Uzr,    g_Uzr);
    cudaGetSymbolAddress((void**)&beffzr, g_beffzr);
    cudaGetSymbolAddress((void**)&probs,  g_probs);
    cudaGetSymbolAddress((void**)&Hbase,  g_H);
    cudaGetSymbolAddress((void**)&zb,     g_z);
    cudaGetSymbolAddress((void**)&Hacc,   g_Hacc);
    cudaGetSymbolAddress((void**)&h1,     g_h1);
    cudaGetSymbolAddress((void**)&Bthi,   g_Bthi);
    cudaGetSymbolAddress((void**)&Btlo,   g_Btlo);
    cudaGetSymbolAddress((void**)&Hpl,    g_Hpl);
    cudaGetSymbolAddress((void**)&Hrpl,   g_Hrpl);
    cudaGetSymbolAddress((void**)&HApl,   g_HApl);
    float* H[2] = {Hbase, Hbase + (size_t)N_NODES * C_DIM};
    const size_t PL = (size_t)N_NODES * KPAIRS;
    uint32_t* Hpl_hi[2] = {Hpl,      Hpl + 2 * PL};
    uint32_t* Hpl_lo[2] = {Hpl + PL, Hpl + 3 * PL};
    uint32_t* Hr_hi = Hrpl;
    uint32_t* Hr_lo = Hrpl + PL;
    uint32_t* HA_hi = HApl;
    uint32_t* HA_lo = HApl + PL;

    cudaFuncSetAttribute(gemm_bf16, cudaFuncAttributeMaxDynamicSharedMemorySize, SMEM_BYTES);

    // setup
    init_state<<<(N_NODES * C_DIM + 255) / 256, 256>>>(H[0], Hacc, deg, Hpl_hi[0], Hpl_lo[0]);
    deg_scatter<<<(N_EDGES + 255) / 256, 256>>>(ei, ea, deg);
    compute_dinv<<<(N_NODES + 255) / 256, 256>>>(deg, dinv);
    agg_init<<<(N_NODES * FT + 255) / 256, 256>>>(x, dinv, agg);
    {
        long long tot = (long long)N_EDGES * FT;
        agg_scatter<<<(unsigned)((tot + 255) / 256), 256>>>(x, ei, ea, dinv, agg);
    }
    softmax12<<<1, 32>>>(att, probs);
    compute_U<<<(3 * F_DIM * C_DIM + 255) / 256, 256>>>(Wg[0], Wg[1], Wg[2], Wl[0], Wl[1], Wl[2], U);
    compute_beff<<<(3 * C_DIM + 255) / 256, 256>>>(bg[0], bg[1], bg[2], Wl[0], Wl[1], Wl[2],
                                                   bl[0], bl[1], bl[2], beff);
    pack_zr<<<(F_DIM * 1024 + 255) / 256, 256>>>(U, beff, Uzr, beffzr);
    transpose_split_B<<<(BT_PAIRS + 255) / 256, 256>>>(Wl[0], Wl[1], Wl[2], W1, Bthi, Btlo);

    dim3 blk(256);
    dim3 gridZR(1024 / BNT, (N_NODES + BMT - 1) / BMT);
    dim3 gridH(512 / BNT, (N_NODES + BMT - 1) / BMT);
    int hin = 0;
    for (int t = 0; t < T_DIM; t++) {
        gemm_bf16<<<gridZR, blk, SMEM_BYTES>>>(Hpl_hi[hin], Hpl_lo[hin],
                                   Bthi + BT_ZR_OFF, Btlo + BT_ZR_OFF,
                                   N_NODES, 1024, 0, t,
                                   agg, Uzr, 1024, beffzr,
                                   H[hin], nullptr, zb,
                                   Hr_hi, Hr_lo, nullptr, nullptr, nullptr, probs);
        gemm_bf16<<<gridH, blk, SMEM_BYTES>>>(Hr_hi, Hr_lo,
                                  Bthi + BT_H_OFF, Btlo + BT_H_OFF,
                                  N_NODES, 512, 2, t,
                                  agg, U + 2 * F_DIM * C_DIM, 512, beff + 2 * C_DIM,
                                  H[hin], zb, H[1 - hin],
                                  Hpl_hi[1 - hin], Hpl_lo[1 - hin],
                                  Hacc, HA_hi, HA_lo, probs);
        hin ^= 1;
    }

    dim3 gridHead(HID_DIM / BNT, (N_NODES + BMT - 1) / BMT);
    gemm_bf16<<<gridHead, blk, SMEM_BYTES>>>(HA_hi, HA_lo,
                                 Bthi + BT_1_OFF, Btlo + BT_1_OFF,
                                 N_NODES, HID_DIM, 3, 0,
                                 nullptr, nullptr, 0, b1,
                                 nullptr, nullptr, h1,
                                 nullptr, nullptr, nullptr, nullptr, nullptr, probs);
    head2<<<(N_NODES * OUT_DIM + 255) / 256, 256>>>(h1, W2, b2, out);
    copy_hidden<<<(N_NODES * C_DIM + 255) / 256, 256>>>(Hacc, out + (size_t)N_NODES * OUT_DIM);
}

// round 14
// speedup vs baseline: 1.3242x; 1.1970x over previous
#include <cuda_runtime.h>
#include <cuda_bf16.h>
#include <cstdint>
#include <math.h>

#define N_NODES 10000
#define N_EDGES 160000
#define F_DIM 4
#define T_DIM 12
#define C_DIM 512
#define HID_DIM 256
#define OUT_DIM 12
#define FT (F_DIM * T_DIM)
#define KPAIRS 256
#define MTILES 79                        // ceil(10000/128)
#define TILES_ZR (MTILES * 8)            // 632
#define TILES_H  (MTILES * 4)            // 316
#define TILES_PER_T (TILES_ZR + TILES_H) // 948
#define TILES_HEAD (MTILES * 2)          // 158
#define TOTAL_TILES (T_DIM * TILES_PER_T + TILES_HEAD)  // 11534
#define GRID_PERSIST 296

// ---------------- scratch ----------------
__device__ float g_deg[N_NODES];
__device__ float g_dinv[N_NODES];
__device__ float g_agg[(size_t)N_NODES * FT];
__device__ float g_U[3 * F_DIM * C_DIM];
__device__ float g_beff[3 * C_DIM];
__device__ float g_Uzr[F_DIM * 2 * C_DIM];
__device__ float g_beffzr[2 * C_DIM];
__device__ float g_probs[T_DIM];
__device__ float g_H[2][(size_t)N_NODES * C_DIM];
__device__ float g_z[(size_t)N_NODES * C_DIM];
__device__ float g_Hacc[(size_t)N_NODES * C_DIM];
__device__ float g_h1[(size_t)N_NODES * HID_DIM];
__device__ uint32_t g_Hpl[2][2][(size_t)N_NODES * KPAIRS];
__device__ uint32_t g_Hrpl[2][(size_t)N_NODES * KPAIRS];
__device__ uint32_t g_HApl[2][(size_t)N_NODES * KPAIRS];
#define BT_ZR_OFF 0
#define BT_H_OFF  (1024 * 256)
#define BT_1_OFF  (1024 * 256 + 512 * 256)
#define BT_PAIRS  ((1024 + 512 + 256) * 256)
__device__ uint32_t g_Bthi[BT_PAIRS];
__device__ uint32_t g_Btlo[BT_PAIRS];
// scheduler state (zeroed every launch)
__device__ int g_cursor;
__device__ int g_zrC[T_DIM * MTILES];
__device__ int g_hC[T_DIM * MTILES];

// ---------------- helpers ----------------
__device__ __forceinline__ uint32_t pack_bf16x2(float a, float b) {
    uint32_t r;
    asm("cvt.rn.bf16x2.f32 %0, %1, %2;" : "=r"(r) : "f"(b), "f"(a));
    return r;
}
__device__ __forceinline__ void split2_store(float v0, float v1,
                                             uint32_t* hip, uint32_t* lop) {
    float h0 = __bfloat162float(__float2bfloat16_rn(v0));
    float h1 = __bfloat162float(__float2bfloat16_rn(v1));
    *hip = pack_bf16x2(v0, v1);
    *lop = pack_bf16x2(v0 - h0, v1 - h1);
}
__device__ __forceinline__ void mma_bf16(float* c, const uint32_t* a, const uint32_t* b) {
    asm volatile(
        "mma.sync.aligned.m16n8k16.row.col.f32.bf16.bf16.f32 "
        "{%0,%1,%2,%3}, {%4,%5,%6,%7}, {%8,%9}, {%0,%1,%2,%3};"
        : "+f"(c[0]), "+f"(c[1]), "+f"(c[2]), "+f"(c[3])
        : "r"(a[0]), "r"(a[1]), "r"(a[2]), "r"(a[3]), "r"(b[0]), "r"(b[1]));
}
#define CP_ASYNC16(dst, src, sz) \
    asm volatile("cp.async.cg.shared.global [%0], [%1], 16, %2;" \
        :: "r"(dst), "l"(src), "r"(sz) : "memory")
#define CP_COMMIT() asm volatile("cp.async.commit_group;" ::: "memory")
#define CP_WAIT(n)  asm volatile("cp.async.wait_group %0;" :: "n"(n) : "memory")

// ---------------- small setup kernels ----------------
__global__ void init_state(float* H0, float* Hacc, float* deg,
                           uint32_t* Hpl_hi, uint32_t* Hpl_lo,
                           int* zrC, int* hC, int* cursor) {
    int idx = blockIdx.x * blockDim.x + threadIdx.x;
    if (idx < N_NODES * C_DIM) { H0[idx] = 0.f; Hacc[idx] = 0.f; }
    if (idx < N_NODES * KPAIRS) { Hpl_hi[idx] = 0u; Hpl_lo[idx] = 0u; }
    if (idx < N_NODES) deg[idx] = 1.f;
    if (idx < T_DIM * MTILES) { zrC[idx] = 0; hC[idx] = 0; }
    if (idx == 0) *cursor = 0;
}
__global__ void deg_scatter(const int* __restrict__ ei, const float* __restrict__ ea,
                            float* __restrict__ deg) {
    int e = blockIdx.x * blockDim.x + threadIdx.x;
    if (e >= N_EDGES) return;
    atomicAdd(&deg[ei[N_EDGES + e]], ea[e]);
}
__global__ void compute_dinv(const float* __restrict__ deg, float* __restrict__ dinv) {
    int i = blockIdx.x * blockDim.x + threadIdx.x;
    if (i >= N_NODES) return;
    dinv[i] = rsqrtf(fmaxf(deg[i], 1e-12f));
}
__global__ void agg_init(const float* __restrict__ x, const float* __restrict__ dinv,
                         float* __restrict__ agg) {
    int idx = blockIdx.x * blockDim.x + threadIdx.x;
    if (idx >= N_NODES * FT) return;
    int i = idx / FT;
    float d = dinv[i];
    agg[idx] = d * d * x[idx];
}
__global__ void agg_scatter(const float* __restrict__ x, const int* __restrict__ ei,
                            const float* __restrict__ ea, const float* __restrict__ dinv,
                            float* __restrict__ agg) {
    long long idx = (long long)blockIdx.x * blockDim.x + threadIdx.x;
    if (idx >= (long long)N_EDGES * FT) return;
    int e = (int)(idx / FT);
    int k = (int)(idx % FT);
    int s = ei[e];
    int d = ei[N_EDGES + e];
    float coef = dinv[s] * ea[e] * dinv[d];
    atomicAdd(&agg[(size_t)d * FT + k], coef * x[(size_t)s * FT + k]);
}
__global__ void softmax12(const float* __restrict__ att, float* __restrict__ probs) {
    if (threadIdx.x == 0) {
        float m = -1e30f;
        for (int i = 0; i < T_DIM; i++) m = fmaxf(m, att[i]);
        float e[T_DIM]; float s = 0.f;
        for (int i = 0; i < T_DIM; i++) { e[i] = expf(att[i] - m); s += e[i]; }
        float inv = 1.f / s;
        for (int i = 0; i < T_DIM; i++) probs[i] = e[i] * inv;
    }
}
__global__ void compute_U(const float* Wzg, const float* Wrg, const float* Whg,
                          const float* Wzl, const float* Wrl, const float* Whl,
                          float* U) {
    int idx = blockIdx.x * blockDim.x + threadIdx.x;
    if (idx >= 3 * F_DIM * C_DIM) return;
    int g = idx / (F_DIM * C_DIM);
    int rem = idx % (F_DIM * C_DIM);
    int f = rem / C_DIM;
    int c = rem % C_DIM;
    const float* Wg = (g == 0) ? Wzg : (g == 1) ? Wrg : Whg;
    const float* Wl = (g == 0) ? Wzl : (g == 1) ? Wrl : Whl;
    float s = 0.f;
    for (int k = 0; k < C_DIM; k++) s += Wg[f * C_DIM + k] * Wl[(size_t)k * C_DIM + c];
    U[idx] = s;
}
__global__ void compute_beff(const float* bzg, const float* brg, const float* bhg,
                             const float* Wzl, const float* Wrl, const float* Whl,
                             const float* bzl, const float* brl, const float* bhl,
                             float* beff) {
    int idx = blockIdx.x * blockDim.x + threadIdx.x;
    if (idx >= 3 * C_DIM) return;
    int g = idx / C_DIM;
    int c = idx % C_DIM;
    const float* bg = (g == 0) ? bzg : (g == 1) ? brg : bhg;
    const float* Wl = (g == 0) ? Wzl : (g == 1) ? Wrl : Whl;
    const float* bl = (g == 0) ? bzl : (g == 1) ? brl : bhl;
    float s = bl[c];
    for (int k = 0; k < C_DIM; k++) s += bg[k] * Wl[(size_t)k * C_DIM + c];
    beff[idx] = s;
}
__global__ void pack_zr(const float* __restrict__ U, const float* __restrict__ beff,
                        float* __restrict__ Uzr, float* __restrict__ beffzr) {
    int idx = blockIdx.x * blockDim.x + threadIdx.x;
    if (idx < F_DIM * 1024) {
        int f = idx >> 10;
        int c = idx & 1023;
        int gt = (c >> 9);
        Uzr[idx] = U[gt * (F_DIM * C_DIM) + f * C_DIM + (c & 511)];
    }
    if (idx < 1024) {
        int gt = idx >> 9;
        beffzr[idx] = beff[gt * C_DIM + (idx & 511)];
    }
}
__global__ void transpose_split_B(const float* Wzl, const float* Wrl, const float* Whl,
                                  const float* W1,
                                  uint32_t* __restrict__ Bthi, uint32_t* __restrict__ Btlo) {
    int idx = blockIdx.x * blockDim.x + threadIdx.x;
    if (idx >= BT_PAIRS) return;
    const int ZR = 1024 * 256, HH = 512 * 256;
    float v0, v1;
    if (idx < ZR) {
        int n = idx >> 8, pk = idx & 255;
        int k0 = pk * 2;
        if (n < 512) {
            v0 = Wzl[(size_t)(C_DIM + k0) * C_DIM + n];
            v1 = Wzl[(size_t)(C_DIM + k0 + 1) * C_DIM + n];
        } else {
            v0 = Wrl[(size_t)(C_DIM + k0) * C_DIM + (n - 512)];
            v1 = Wrl[(size_t)(C_DIM + k0 + 1) * C_DIM + (n - 512)];
        }
    } else if (idx < ZR + HH) {
        int r = idx - ZR;
        int n = r >> 8, pk = r & 255;
        int k0 = pk * 2;
        v0 = Whl[(size_t)(C_DIM + k0) * C_DIM + n];
        v1 = Whl[(size_t)(C_DIM + k0 + 1) * C_DIM + n];
    } else {
        int r = idx - ZR - HH;
        int n = r >> 8, pk = r & 255;
        int k0 = pk * 2;
        v0 = W1[(size_t)k0 * HID_DIM + n];
        v1 = W1[(size_t)(k0 + 1) * HID_DIM + n];
    }
    split2_store(v0, v1, &Bthi[idx], &Btlo[idx]);
}

// ---------------- persistent megakernel ----------------
#define BMT 128
#define SPAD 20
#define PLANE_U32 (BMT * SPAD)       // 2560
#define BUF_U32   (4 * PLANE_U32)    // 10240
#define SMEM_U32  (2 * BUF_U32 + BMT * F_DIM)
#define SMEM_BYTES (SMEM_U32 * 4)    // 83968

__global__ __launch_bounds__(256, 2) void megakernel(
    const uint32_t* __restrict__ Hpl,    // [2 bufs][hi/lo][PL]
    const uint32_t* __restrict__ Hrpl,   // [hi/lo][PL]
    const uint32_t* __restrict__ HApl,   // [hi/lo][PL]
    const uint32_t* __restrict__ Bthi, const uint32_t* __restrict__ Btlo,
    float* __restrict__ Hf,              // [2 bufs][N*C]
    float* __restrict__ zb,
    float* __restrict__ Hacc,
    float* __restrict__ h1,
    const float* __restrict__ agg,
    const float* __restrict__ Uzr, const float* __restrict__ Ug,
    const float* __restrict__ beffzr, const float* __restrict__ beffg,
    const float* __restrict__ b1,
    const float* __restrict__ probs,
    int* __restrict__ cursor, int* __restrict__ zrC, int* __restrict__ hC)
{
    extern __shared__ uint32_t smem[];
    float* aggS = (float*)(smem + 2 * BUF_U32);
    __shared__ int s_id;

    const int tid = threadIdx.x;
    const int wid = tid >> 5;
    const int lane = tid & 31;
    const int g8 = lane >> 2;
    const int tig = lane & 3;
    const int wm = wid >> 2;
    const int wn = wid & 3;
    const int f_r = tid >> 1;
    const int f_q = (tid & 1) * 2;
    const size_t PL = (size_t)N_NODES * KPAIRS;
    const size_t NH = (size_t)N_NODES * C_DIM;
    const uint32_t smem_fill0 =
        (uint32_t)__cvta_generic_to_shared(smem + f_r * SPAD + f_q * 4);

    for (;;) {
        if (tid == 0) s_id = atomicAdd(cursor, 1);
        __syncthreads();
        const int id = s_id;
        if (id >= TOTAL_TILES) break;

        // ---- decode tile ----
        int type, t, mt, nt;          // type: 0=zr, 1=h, 2=head
        if (id < T_DIM * TILES_PER_T) {
            t = id / TILES_PER_T;
            int r = id % TILES_PER_T;
            if (r < TILES_ZR) { type = 0; mt = r >> 3; nt = r & 7; }
            else { int r2 = r - TILES_ZR; type = 1; mt = r2 >> 2; nt = r2 & 3; }
        } else {
            int r = id - T_DIM * TILES_PER_T;
            type = 2; t = 0; mt = r >> 1; nt = r & 1;
        }
        const int row0 = mt * BMT;
        const int col0 = nt * 128;

        // ---- wait deps ----
        if (tid == 0) {
            if (type == 0) {
                if (t > 0) { int* c = &hC[(t - 1) * MTILES + mt];
                    while (atomicAdd(c, 0) < 4) __nanosleep(64); }
            } else if (type == 1) {
                int* c = &zrC[t * MTILES + mt];
                while (atomicAdd(c, 0) < 8) __nanosleep(64);
            } else {
                int* c = &hC[(T_DIM - 1) * MTILES + mt];
                while (atomicAdd(c, 0) < 4) __nanosleep(64);
            }
        }
        __syncthreads();

        // ---- per-tile operand pointers ----
        const uint32_t *Ahi_g, *Alo_g, *Bh_g, *Bl_g;
        const float *U, *beff;
        int ustride = 512;
        if (type == 0) {
            const int buf = t & 1;
            Ahi_g = Hpl + (size_t)buf * 2 * PL;
            Alo_g = Ahi_g + PL;
            Bh_g = Bthi + BT_ZR_OFF; Bl_g = Btlo + BT_ZR_OFF;
            U = Uzr; beff = beffzr; ustride = 1024;
        } else if (type == 1) {
            Ahi_g = Hrpl; Alo_g = Hrpl + PL;
            Bh_g = Bthi + BT_H_OFF; Bl_g = Btlo + BT_H_OFF;
            U = Ug + 2 * F_DIM * C_DIM; beff = beffg + 2 * C_DIM;
        } else {
            Ahi_g = HApl; Alo_g = HApl + PL;
            Bh_g = Bthi + BT_1_OFF; Bl_g = Btlo + BT_1_OFF;
            U = Ug; beff = b1;   // U unused in mode 3
        }

        if (type != 2) {
            for (int i = tid; i < BMT * F_DIM; i += 256) {
                int r = i >> 2, f = i & 3;
                aggS[i] = (row0 + r < N_NODES)
                        ? __ldcg(agg + (size_t)(row0 + r) * FT + f * T_DIM + t) : 0.f;
            }
        }

        const int a_gr = row0 + f_r;
        const uint32_t a_sz = (a_gr < N_NODES) ? 16u : 0u;
        const uint4* Ag_hi = (const uint4*)Ahi_g + (size_t)a_gr * 64 + f_q;
        const uint4* Ag_lo = (const uint4*)Alo_g + (size_t)a_gr * 64 + f_q;
        const uint4* Bg_hi = (const uint4*)Bh_g + (size_t)(col0 + f_r) * 64 + f_q;
        const uint4* Bg_lo = (const uint4*)Bl_g + (size_t)(col0 + f_r) * 64 + f_q;

#define FILL_CHUNK(kc_, buf_) do {                                          \
        int _k4 = (kc_) * 4;                                                \
        uint32_t _d = smem_fill0 + (buf_) * (BUF_U32 * 4);                  \
        CP_ASYNC16(_d,                  Ag_hi + _k4,     a_sz);             \
        CP_ASYNC16(_d + 16,             Ag_hi + _k4 + 1, a_sz);             \
        CP_ASYNC16(_d + PLANE_U32*4,      Ag_lo + _k4,     a_sz);           \
        CP_ASYNC16(_d + PLANE_U32*4 + 16, Ag_lo + _k4 + 1, a_sz);           \
        CP_ASYNC16(_d + 2*PLANE_U32*4,      Bg_hi + _k4,     16u);          \
        CP_ASYNC16(_d + 2*PLANE_U32*4 + 16, Bg_hi + _k4 + 1, 16u);          \
        CP_ASYNC16(_d + 3*PLANE_U32*4,      Bg_lo + _k4,     16u);          \
        CP_ASYNC16(_d + 3*PLANE_U32*4 + 16, Bg_lo + _k4 + 1, 16u);          \
        CP_COMMIT();                                                        \
    } while (0)

        float acc[4][4][4];
#pragma unroll
        for (int a = 0; a < 4; a++)
#pragma unroll
            for (int b = 0; b < 4; b++)
#pragma unroll
                for (int c = 0; c < 4; c++) acc[a][b][c] = 0.f;

        FILL_CHUNK(0, 0);

        for (int kc = 0; kc < 16; kc++) {
            if (kc < 15) {
                FILL_CHUNK(kc + 1, (kc + 1) & 1);
                CP_WAIT(1);
            } else {
                CP_WAIT(0);
            }
            __syncthreads();

            const uint32_t* Ah = smem + (kc & 1) * BUF_U32;
            const uint32_t* Al = Ah + PLANE_U32;
            const uint32_t* Bh = Ah + 2 * PLANE_U32;
            const uint32_t* Bl = Ah + 3 * PLANE_U32;

#pragma unroll
            for (int kb = 0; kb < 2; kb++) {
                const int ko = kb * 8;
                uint32_t bh[4][2], bl[4][2];
#pragma unroll
                for (int ntt = 0; ntt < 4; ntt++) {
                    int n = wn * 32 + ntt * 8 + g8;
                    bh[ntt][0] = Bh[n * SPAD + ko + tig];
                    bh[ntt][1] = Bh[n * SPAD + ko + tig + 4];
                    bl[ntt][0] = Bl[n * SPAD + ko + tig];
                    bl[ntt][1] = Bl[n * SPAD + ko + tig + 4];
                }
#pragma unroll
                for (int mtt = 0; mtt < 4; mtt++) {
                    int r = wm * 64 + mtt * 16 + g8;
                    uint32_t ah[4], al[4];
                    ah[0] = Ah[r * SPAD + ko + tig];
                    ah[1] = Ah[(r + 8) * SPAD + ko + tig];
                    ah[2] = Ah[r * SPAD + ko + tig + 4];
                    ah[3] = Ah[(r + 8) * SPAD + ko + tig + 4];
                    al[0] = Al[r * SPAD + ko + tig];
                    al[1] = Al[(r + 8) * SPAD + ko + tig];
                    al[2] = Al[r * SPAD + ko + tig + 4];
                    al[3] = Al[(r + 8) * SPAD + ko + tig + 4];
#pragma unroll
                    for (int ntt = 0; ntt < 4; ntt++) mma_bf16(acc[mtt][ntt], ah, bh[ntt]);
#pragma unroll
                    for (int ntt = 0; ntt < 4; ntt++) mma_bf16(acc[mtt][ntt], ah, bl[ntt]);
#pragma unroll
                    for (int ntt = 0; ntt < 4; ntt++) mma_bf16(acc[mtt][ntt], al, bh[ntt]);
                }
            }
            __syncthreads();
        }
#undef FILL_CHUNK

        // ---- epilogue ----
        const float* Hin = Hf + (size_t)(t & 1) * NH;
        float* Hout = Hf + (size_t)((t + 1) & 1) * NH;
        uint32_t* pl_hi = (uint32_t*)Hpl + (size_t)((t + 1) & 1) * 2 * PL;
        uint32_t* pl_lo = pl_hi + PL;
        uint32_t* hr_hi = (uint32_t*)Hrpl;
        uint32_t* hr_lo = hr_hi + PL;
        uint32_t* ha_hi = (uint32_t*)HApl;
        uint32_t* ha_lo = ha_hi + PL;
        const float p = (type == 1) ? probs[t] : 0.f;
        const bool last_t = (type == 1) && (t == T_DIM - 1);

#pragma unroll
        for (int mtt = 0; mtt < 4; mtt++) {
#pragma unroll
            for (int i = 0; i < 2; i++) {
                int rl = wm * 64 + mtt * 16 + g8 + i * 8;
                int gr = row0 + rl;
                if (gr >= N_NODES) continue;
                float a0 = 0.f, a1 = 0.f, a2 = 0.f, a3 = 0.f;
                if (type != 2) {
                    a0 = aggS[rl * 4 + 0]; a1 = aggS[rl * 4 + 1];
                    a2 = aggS[rl * 4 + 2]; a3 = aggS[rl * 4 + 3];
                }
#pragma unroll
                for (int ntt = 0; ntt < 4; ntt++) {
                    const int cg0 = col0 + wn * 32 + ntt * 8 + tig * 2;
                    float vv[2];
#pragma unroll
                    for (int jj = 0; jj < 2; jj++) {
                        int cg = cg0 + jj;
                        float v = acc[mtt][ntt][i * 2 + jj] + beff[cg];
                        if (type != 2)
                            v += a0 * U[cg] + a1 * U[ustride + cg]
                               + a2 * U[2 * ustride + cg] + a3 * U[3 * ustride + cg];
                        vv[jj] = v;
                    }
                    if (type == 0) {
                        if (cg0 < 512) {
                            zb[(size_t)gr * C_DIM + cg0]     = 1.f / (1.f + expf(-vv[0]));
                            zb[(size_t)gr * C_DIM + cg0 + 1] = 1.f / (1.f + expf(-vv[1]));
                        } else {
                            size_t o = (size_t)gr * C_DIM + (cg0 - 512);
                            float hr0 = __ldcg(Hin + o)     * (1.f / (1.f + expf(-vv[0])));
                            float hr1 = __ldcg(Hin + o + 1) * (1.f / (1.f + expf(-vv[1])));
                            size_t pp = (size_t)gr * KPAIRS + ((cg0 - 512) >> 1);
                            split2_store(hr0, hr1, &hr_hi[pp], &hr_lo[pp]);
                        }
                    } else if (type == 1) {
                        size_t o = (size_t)gr * C_DIM + cg0;
                        float z0 = __ldcg(zb + o), z1 = __ldcg(zb + o + 1);
                        float hn0 = z0 * __ldcg(Hin + o)     + (1.f - z0) * tanhf(vv[0]);
                        float hn1 = z1 * __ldcg(Hin + o + 1) + (1.f - z1) * tanhf(vv[1]);
                        Hout[o]     = hn0;
                        Hout[o + 1] = hn1;
                        size_t pp = (size_t)gr * KPAIRS + (cg0 >> 1);
                        split2_store(hn0, hn1, &pl_hi[pp], &pl_lo[pp]);
                        float ha0 = __ldcg(Hacc + o)     + p * hn0;
                        float ha1 = __ldcg(Hacc + o + 1) + p * hn1;
                        Hacc[o]     = ha0;
                        Hacc[o + 1] = ha1;
                        if (last_t)
                            split2_store(fmaxf(ha0, 0.f), fmaxf(ha1, 0.f),
                                         &ha_hi[pp], &ha_lo[pp]);
                    } else {
                        h1[(size_t)gr * HID_DIM + cg0]     = fmaxf(vv[0], 0.f);
                        h1[(size_t)gr * HID_DIM + cg0 + 1] = fmaxf(vv[1], 0.f);
                    }
                }
            }
        }

        // ---- publish ----
        __threadfence();
        __syncthreads();
        if (tid == 0) {
            if (type == 0)      atomicAdd(&zrC[t * MTILES + mt], 1);
            else if (type == 1) atomicAdd(&hC[t * MTILES + mt], 1);
        }
        __syncthreads();
    }
}

// out[i,j] = h1[i,:] @ W2[:,j] + b2[j]
__global__ void head2(const float* __restrict__ h1, const float* __restrict__ W2,
                      const float* __restrict__ b2, float* __restrict__ out) {
    int idx = blockIdx.x * blockDim.x + threadIdx.x;
    if (idx >= N_NODES * OUT_DIM) return;
    int i = idx / OUT_DIM;
    int j = idx % OUT_DIM;
    float s = b2[j];
    const float* hr = h1 + (size_t)i * HID_DIM;
    for (int k = 0; k < HID_DIM; k++) s += hr[k] * W2[k * OUT_DIM + j];
    out[idx] = s;
}
__global__ void copy_hidden(const float* __restrict__ Hacc, float* __restrict__ out) {
    int idx = blockIdx.x * blockDim.x + threadIdx.x;
    if (idx >= N_NODES * C_DIM) return;
    out[idx] = Hacc[idx];
}

// ---------------- host launcher ----------------
extern "C" void kernel_launch(void* const* d_in, const int* in_sizes, int n_in,
                              void* d_out, int out_size) {
    const float* x   = (const float*)d_in[0];
    const int*   ei  = (const int*)d_in[1];
    const float* ea  = (const float*)d_in[2];
    const float* att = (const float*)d_in[3];
    const float* Wg[3] = {(const float*)d_in[4],  (const float*)d_in[8],  (const float*)d_in[12]};
    const float* bg[3] = {(const float*)d_in[5],  (const float*)d_in[9],  (const float*)d_in[13]};
    const float* Wl[3] = {(const float*)d_in[6],  (const float*)d_in[10], (const float*)d_in[14]};
    const float* bl[3] = {(const float*)d_in[7],  (const float*)d_in[11], (const float*)d_in[15]};
    const float* W1 = (const float*)d_in[16];
    const float* b1 = (const float*)d_in[17];
    const float* W2 = (const float*)d_in[18];
    const float* b2 = (const float*)d_in[19];
    float* out = (float*)d_out;

    float *deg, *dinv, *agg, *U, *beff, *Uzr, *beffzr, *probs, *Hbase, *zb, *Hacc, *h1;
    uint32_t *Bthi, *Btlo, *Hpl, *Hrpl, *HApl;
    int *cursor, *zrC, *hC;
    cudaGetSymbolAddress((void**)&deg,    g_deg);
    cudaGetSymbolAddress((void**)&dinv,   g_dinv);
    cudaGetSymbolAddress((void**)&agg,    g_agg);
    cudaGetSymbolAddress((void**)&U,      g_U);
    cudaGetSymbolAddress((void**)&beff,   g_beff);
    cudaGetSymbolAddress((void**)&Uzr,    g_Uzr);
    cudaGetSymbolAddress((void**)&beffzr, g_beffzr);
    cudaGetSymbolAddress((void**)&probs,  g_probs);
    cudaGetSymbolAddress((void**)&Hbase,  g_H);
    cudaGetSymbolAddress((void**)&zb,     g_z);
    cudaGetSymbolAddress((void**)&Hacc,   g_Hacc);
    cudaGetSymbolAddress((void**)&h1,     g_h1);
    cudaGetSymbolAddress((void**)&Bthi,   g_Bthi);
    cudaGetSymbolAddress((void**)&Btlo,   g_Btlo);
    cudaGetSymbolAddress((void**)&Hpl,    g_Hpl);
    cudaGetSymbolAddress((void**)&Hrpl,   g_Hrpl);
    cudaGetSymbolAddress((void**)&HApl,   g_HApl);
    cudaGetSymbolAddress((void**)&cursor, g_cursor);
    cudaGetSymbolAddress((void**)&zrC,    g_zrC);
    cudaGetSymbolAddress((void**)&hC,     g_hC);
    const size_t PL = (size_t)N_NODES * KPAIRS;

    cudaFuncSetAttribute(megakernel, cudaFuncAttributeMaxDynamicSharedMemorySize, SMEM_BYTES);

    // setup
    init_state<<<(N_NODES * C_DIM + 255) / 256, 256>>>(Hbase, Hacc, deg,
                                                       Hpl, Hpl + PL, zrC, hC, cursor);
    deg_scatter<<<(N_EDGES + 255) / 256, 256>>>(ei, ea, deg);
    compute_dinv<<<(N_NODES + 255) / 256, 256>>>(deg, dinv);
    agg_init<<<(N_NODES * FT + 255) / 256, 256>>>(x, dinv, agg);
    {
        long long tot = (long long)N_EDGES * FT;
        agg_scatter<<<(unsigned)((tot + 255) / 256), 256>>>(x, ei, ea, dinv, agg);
    }
    softmax12<<<1, 32>>>(att, probs);
    compute_U<<<(3 * F_DIM * C_DIM + 255) / 256, 256>>>(Wg[0], Wg[1], Wg[2], Wl[0], Wl[1], Wl[2], U);
    compute_beff<<<(3 * C_DIM + 255) / 256, 256>>>(bg[0], bg[1], bg[2], Wl[0], Wl[1], Wl[2],
                                                   bl[0], bl[1], bl[2], beff);
    pack_zr<<<(F_DIM * 1024 + 255) / 256, 256>>>(U, beff, Uzr, beffzr);
    transpose_split_B<<<(BT_PAIRS + 255) / 256, 256>>>(Wl[0], Wl[1], Wl[2], W1, Bthi, Btlo);

    // one persistent launch covers all 12 timesteps (zr + h) + head1
    megakernel<<<GRID_PERSIST, 256, SMEM_BYTES>>>(
        Hpl, Hrpl, HApl, Bthi, Btlo,
        Hbase, zb, Hacc, h1,
        agg, Uzr, U, beffzr, beff, b1, probs,
        cursor, zrC, hC);

    head2<<<(N_NODES * OUT_DIM + 255) / 256, 256>>>(h1, W2, b2, out);
    copy_hidden<<<(N_NODES * C_DIM + 255) / 256, 256>>>(Hacc, out + (size_t)N_NODES * OUT_DIM);
}

// round 15
// speedup vs baseline: 1.6339x; 1.2339x over previous
#include <cuda_runtime.h>
#include <cuda_fp16.h>
#include <cstdint>
#include <math.h>

#define N_NODES 10000
#define N_EDGES 160000
#define F_DIM 4
#define T_DIM 12
#define C_DIM 512
#define HID_DIM 256
#define OUT_DIM 12
#define FT (F_DIM * T_DIM)
#define KPAIRS 256
#define MTILES 79
#define TILES_ZR (MTILES * 8)            // 632
#define TILES_H  (MTILES * 4)            // 316
#define TILES_PER_T (TILES_ZR + TILES_H) // 948
#define TILES_HEAD (MTILES * 2)          // 158
#define TOTAL_TILES (T_DIM * TILES_PER_T + TILES_HEAD)  // 11534
#define GRID_PERSIST 296

// ---------------- scratch ----------------
__device__ float g_deg[N_NODES];
__device__ float g_dinv[N_NODES];
__device__ float g_agg[(size_t)N_NODES * FT];
__device__ float g_U[3 * F_DIM * C_DIM];
__device__ float g_beff[3 * C_DIM];
__device__ float g_Uzr[F_DIM * 2 * C_DIM];
__device__ float g_beffzr[2 * C_DIM];
__device__ float g_probs[T_DIM];
__device__ float g_H[2][(size_t)N_NODES * C_DIM];
__device__ float g_z[(size_t)N_NODES * C_DIM];
__device__ float g_Hacc[(size_t)N_NODES * C_DIM];
__device__ float g_h1[(size_t)N_NODES * HID_DIM];
// fp16 hi/lo packed planes (A operands), [node][256] u32
__device__ uint32_t g_Hpl[2][2][(size_t)N_NODES * KPAIRS];
__device__ uint32_t g_Hrpl[2][(size_t)N_NODES * KPAIRS];
__device__ uint32_t g_HApl[2][(size_t)N_NODES * KPAIRS];
// transposed fp16 pair-packed weights (single plane)
#define BT_ZR_OFF 0
#define BT_H_OFF  (1024 * 256)
#define BT_1_OFF  (1024 * 256 + 512 * 256)
#define BT_PAIRS  ((1024 + 512 + 256) * 256)
__device__ uint32_t g_Bt[BT_PAIRS];
// scheduler state
__device__ int g_cursor;
__device__ int g_zrC[T_DIM * MTILES];
__device__ int g_hC[T_DIM * MTILES];

// ---------------- helpers ----------------
__device__ __forceinline__ uint32_t pack_f16x2(float a, float b) {
    __half2 h = __floats2half2_rn(a, b);
    return *(uint32_t*)&h;
}
__device__ __forceinline__ void split2_store_f16(float v0, float v1,
                                                 uint32_t* hip, uint32_t* lop) {
    __half h0 = __float2half_rn(v0);
    __half h1 = __float2half_rn(v1);
    __half2 hp = __halves2half2(h0, h1);
    *hip = *(uint32_t*)&hp;
    *lop = pack_f16x2(v0 - __half2float(h0), v1 - __half2float(h1));
}
__device__ __forceinline__ void mma_f16(float* c, const uint32_t* a, const uint32_t* b) {
    asm volatile(
        "mma.sync.aligned.m16n8k16.row.col.f32.f16.f16.f32 "
        "{%0,%1,%2,%3}, {%4,%5,%6,%7}, {%8,%9}, {%0,%1,%2,%3};"
        : "+f"(c[0]), "+f"(c[1]), "+f"(c[2]), "+f"(c[3])
        : "r"(a[0]), "r"(a[1]), "r"(a[2]), "r"(a[3]), "r"(b[0]), "r"(b[1]));
}
#define CP_ASYNC16(dst, src, sz) \
    asm volatile("cp.async.cg.shared.global [%0], [%1], 16, %2;" \
        :: "r"(dst), "l"(src), "r"(sz) : "memory")
#define CP_COMMIT() asm volatile("cp.async.commit_group;" ::: "memory")
#define CP_WAIT(n)  asm volatile("cp.async.wait_group %0;" :: "n"(n) : "memory")

// ---------------- small setup kernels ----------------
__global__ void init_state(float* H0, float* Hacc, float* deg,
                           uint32_t* Hpl_hi, uint32_t* Hpl_lo,
                           int* zrC, int* hC, int* cursor) {
    int idx = blockIdx.x * blockDim.x + threadIdx.x;
    if (idx < N_NODES * C_DIM) { H0[idx] = 0.f; Hacc[idx] = 0.f; }
    if (idx < N_NODES * KPAIRS) { Hpl_hi[idx] = 0u; Hpl_lo[idx] = 0u; }
    if (idx < N_NODES) deg[idx] = 1.f;
    if (idx < T_DIM * MTILES) { zrC[idx] = 0; hC[idx] = 0; }
    if (idx == 0) *cursor = 0;
}
__global__ void deg_scatter(const int* __restrict__ ei, const float* __restrict__ ea,
                            float* __restrict__ deg) {
    int e = blockIdx.x * blockDim.x + threadIdx.x;
    if (e >= N_EDGES) return;
    atomicAdd(&deg[ei[N_EDGES + e]], ea[e]);
}
__global__ void compute_dinv(const float* __restrict__ deg, float* __restrict__ dinv) {
    int i = blockIdx.x * blockDim.x + threadIdx.x;
    if (i >= N_NODES) return;
    dinv[i] = rsqrtf(fmaxf(deg[i], 1e-12f));
}
__global__ void agg_init(const float* __restrict__ x, const float* __restrict__ dinv,
                         float* __restrict__ agg) {
    int idx = blockIdx.x * blockDim.x + threadIdx.x;
    if (idx >= N_NODES * FT) return;
    int i = idx / FT;
    float d = dinv[i];
    agg[idx] = d * d * x[idx];
}
__global__ void agg_scatter(const float* __restrict__ x, const int* __restrict__ ei,
                            const float* __restrict__ ea, const float* __restrict__ dinv,
                            float* __restrict__ agg) {
    long long idx = (long long)blockIdx.x * blockDim.x + threadIdx.x;
    if (idx >= (long long)N_EDGES * FT) return;
    int e = (int)(idx / FT);
    int k = (int)(idx % FT);
    int s = ei[e];
    int d = ei[N_EDGES + e];
    float coef = dinv[s] * ea[e] * dinv[d];
    atomicAdd(&agg[(size_t)d * FT + k], coef * x[(size_t)s * FT + k]);
}
__global__ void softmax12(const float* __restrict__ att, float* __restrict__ probs) {
    if (threadIdx.x == 0) {
        float m = -1e30f;
        for (int i = 0; i < T_DIM; i++) m = fmaxf(m, att[i]);
        float e[T_DIM]; float s = 0.f;
        for (int i = 0; i < T_DIM; i++) { e[i] = expf(att[i] - m); s += e[i]; }
        float inv = 1.f / s;
        for (int i = 0; i < T_DIM; i++) probs[i] = e[i] * inv;
    }
}
__global__ void compute_U(const float* Wzg, const float* Wrg, const float* Whg,
                          const float* Wzl, const float* Wrl, const float* Whl,
                          float* U) {
    int idx = blockIdx.x * blockDim.x + threadIdx.x;
    if (idx >= 3 * F_DIM * C_DIM) return;
    int g = idx / (F_DIM * C_DIM);
    int rem = idx % (F_DIM * C_DIM);
    int f = rem / C_DIM;
    int c = rem % C_DIM;
    const float* Wg = (g == 0) ? Wzg : (g == 1) ? Wrg : Whg;
    const float* Wl = (g == 0) ? Wzl : (g == 1) ? Wrl : Whl;
    float s = 0.f;
    for (int k = 0; k < C_DIM; k++) s += Wg[f * C_DIM + k] * Wl[(size_t)k * C_DIM + c];
    U[idx] = s;
}
__global__ void compute_beff(const float* bzg, const float* brg, const float* bhg,
                             const float* Wzl, const float* Wrl, const float* Whl,
                             const float* bzl, const float* brl, const float* bhl,
                             float* beff) {
    int idx = blockIdx.x * blockDim.x + threadIdx.x;
    if (idx >= 3 * C_DIM) return;
    int g = idx / C_DIM;
    int c = idx % C_DIM;
    const float* bg = (g == 0) ? bzg : (g == 1) ? brg : bhg;
    const float* Wl = (g == 0) ? Wzl : (g == 1) ? Wrl : Whl;
    const float* bl = (g == 0) ? bzl : (g == 1) ? brl : bhl;
    float s = bl[c];
    for (int k = 0; k < C_DIM; k++) s += bg[k] * Wl[(size_t)k * C_DIM + c];
    beff[idx] = s;
}
__global__ void pack_zr(const float* __restrict__ U, const float* __restrict__ beff,
                        float* __restrict__ Uzr, float* __restrict__ beffzr) {
    int idx = blockIdx.x * blockDim.x + threadIdx.x;
    if (idx < F_DIM * 1024) {
        int f = idx >> 10;
        int c = idx & 1023;
        int gt = (c >> 9);
        Uzr[idx] = U[gt * (F_DIM * C_DIM) + f * C_DIM + (c & 511)];
    }
    if (idx < 1024) {
        int gt = idx >> 9;
        beffzr[idx] = beff[gt * C_DIM + (idx & 511)];
    }
}
// transposed fp16 pair-packed weight plane (single precision plane)
__global__ void transpose_B_f16(const float* Wzl, const float* Wrl, const float* Whl,
                                const float* W1, uint32_t* __restrict__ Bt) {
    int idx = blockIdx.x * blockDim.x + threadIdx.x;
    if (idx >= BT_PAIRS) return;
    const int ZR = 1024 * 256, HH = 512 * 256;
    float v0, v1;
    if (idx < ZR) {
        int n = idx >> 8, pk = idx & 255;
        int k0 = pk * 2;
        if (n < 512) {
            v0 = Wzl[(size_t)(C_DIM + k0) * C_DIM + n];
            v1 = Wzl[(size_t)(C_DIM + k0 + 1) * C_DIM + n];
        } else {
            v0 = Wrl[(size_t)(C_DIM + k0) * C_DIM + (n - 512)];
            v1 = Wrl[(size_t)(C_DIM + k0 + 1) * C_DIM + (n - 512)];
        }
    } else if (idx < ZR + HH) {
        int r = idx - ZR;
        int n = r >> 8, pk = r & 255;
        int k0 = pk * 2;
        v0 = Whl[(size_t)(C_DIM + k0) * C_DIM + n];
        v1 = Whl[(size_t)(C_DIM + k0 + 1) * C_DIM + n];
    } else {
        int r = idx - ZR - HH;
        int n = r >> 8, pk = r & 255;
        int k0 = pk * 2;
        v0 = W1[(size_t)k0 * HID_DIM + n];
        v1 = W1[(size_t)(k0 + 1) * HID_DIM + n];
    }
    Bt[idx] = pack_f16x2(v0, v1);
}

// ---------------- persistent megakernel (fp16 2-term split) ----------------
#define BMT 128
#define SPAD 20
#define PLANE_U32 (BMT * SPAD)       // 2560
#define BUF_U32   (3 * PLANE_U32)    // 7680 (Ahi, Alo, B)
#define SMEM_U32  (2 * BUF_U32 + BMT * F_DIM)
#define SMEM_BYTES (SMEM_U32 * 4)    // 63488

__global__ __launch_bounds__(256, 2) void megakernel(
    const uint32_t* __restrict__ Hpl,    // [2 bufs][hi/lo][PL]
    const uint32_t* __restrict__ Hrpl,   // [hi/lo][PL]
    const uint32_t* __restrict__ HApl,   // [hi/lo][PL]
    const uint32_t* __restrict__ Bt,
    float* __restrict__ Hf,
    float* __restrict__ zb,
    float* __restrict__ Hacc,
    float* __restrict__ h1,
    const float* __restrict__ agg,
    const float* __restrict__ Uzr, const float* __restrict__ Ug,
    const float* __restrict__ beffzr, const float* __restrict__ beffg,
    const float* __restrict__ b1,
    const float* __restrict__ probs,
    int* __restrict__ cursor, int* __restrict__ zrC, int* __restrict__ hC)
{
    extern __shared__ uint32_t smem[];
    float* aggS = (float*)(smem + 2 * BUF_U32);
    __shared__ int s_id;

    const int tid = threadIdx.x;
    const int wid = tid >> 5;
    const int lane = tid & 31;
    const int g8 = lane >> 2;
    const int tig = lane & 3;
    const int wm = wid >> 2;
    const int wn = wid & 3;
    const int f_r = tid >> 1;
    const int f_q = (tid & 1) * 2;
    const size_t PL = (size_t)N_NODES * KPAIRS;
    const size_t NH = (size_t)N_NODES * C_DIM;
    const uint32_t smem_fill0 =
        (uint32_t)__cvta_generic_to_shared(smem + f_r * SPAD + f_q * 4);

    for (;;) {
        if (tid == 0) s_id = atomicAdd(cursor, 1);
        __syncthreads();
        const int id = s_id;
        if (id >= TOTAL_TILES) break;

        // ---- decode tile ----
        int type, t, mt, nt;
        if (id < T_DIM * TILES_PER_T) {
            t = id / TILES_PER_T;
            int r = id % TILES_PER_T;
            if (r < TILES_ZR) { type = 0; mt = r >> 3; nt = r & 7; }
            else { int r2 = r - TILES_ZR; type = 1; mt = r2 >> 2; nt = r2 & 3; }
        } else {
            int r = id - T_DIM * TILES_PER_T;
            type = 2; t = 0; mt = r >> 1; nt = r & 1;
        }
        const int row0 = mt * BMT;
        const int col0 = nt * 128;

        // ---- wait deps ----
        if (tid == 0) {
            if (type == 0) {
                if (t > 0) { int* c = &hC[(t - 1) * MTILES + mt];
                    while (atomicAdd(c, 0) < 4) __nanosleep(64); }
            } else if (type == 1) {
                int* c = &zrC[t * MTILES + mt];
                while (atomicAdd(c, 0) < 8) __nanosleep(64);
            } else {
                int* c = &hC[(T_DIM - 1) * MTILES + mt];
                while (atomicAdd(c, 0) < 4) __nanosleep(64);
            }
        }
        __syncthreads();

        // ---- per-tile operand pointers ----
        const uint32_t *Ahi_g, *Alo_g, *Bg;
        const float *U, *beff;
        int ustride = 512;
        if (type == 0) {
            const int buf = t & 1;
            Ahi_g = Hpl + (size_t)buf * 2 * PL;
            Alo_g = Ahi_g + PL;
            Bg = Bt + BT_ZR_OFF;
            U = Uzr; beff = beffzr; ustride = 1024;
        } else if (type == 1) {
            Ahi_g = Hrpl; Alo_g = Hrpl + PL;
            Bg = Bt + BT_H_OFF;
            U = Ug + 2 * F_DIM * C_DIM; beff = beffg + 2 * C_DIM;
        } else {
            Ahi_g = HApl; Alo_g = HApl + PL;
            Bg = Bt + BT_1_OFF;
            U = Ug; beff = b1;
        }

        if (type != 2) {
            for (int i = tid; i < BMT * F_DIM; i += 256) {
                int r = i >> 2, f = i & 3;
                aggS[i] = (row0 + r < N_NODES)
                        ? __ldcg(agg + (size_t)(row0 + r) * FT + f * T_DIM + t) : 0.f;
            }
        }

        const int a_gr = row0 + f_r;
        const uint32_t a_sz = (a_gr < N_NODES) ? 16u : 0u;
        const uint4* Ag_hi = (const uint4*)Ahi_g + (size_t)a_gr * 64 + f_q;
        const uint4* Ag_lo = (const uint4*)Alo_g + (size_t)a_gr * 64 + f_q;
        const uint4* Bg_p  = (const uint4*)Bg + (size_t)(col0 + f_r) * 64 + f_q;

#define FILL_CHUNK(kc_, buf_) do {                                          \
        int _k4 = (kc_) * 4;                                                \
        uint32_t _d = smem_fill0 + (buf_) * (BUF_U32 * 4);                  \
        CP_ASYNC16(_d,                    Ag_hi + _k4,     a_sz);           \
        CP_ASYNC16(_d + 16,               Ag_hi + _k4 + 1, a_sz);           \
        CP_ASYNC16(_d + PLANE_U32*4,      Ag_lo + _k4,     a_sz);           \
        CP_ASYNC16(_d + PLANE_U32*4 + 16, Ag_lo + _k4 + 1, a_sz);           \
        CP_ASYNC16(_d + 2*PLANE_U32*4,      Bg_p + _k4,     16u);           \
        CP_ASYNC16(_d + 2*PLANE_U32*4 + 16, Bg_p + _k4 + 1, 16u);           \
        CP_COMMIT();                                                        \
    } while (0)

        float acc[4][4][4];
#pragma unroll
        for (int a = 0; a < 4; a++)
#pragma unroll
            for (int b = 0; b < 4; b++)
#pragma unroll
                for (int c = 0; c < 4; c++) acc[a][b][c] = 0.f;

        FILL_CHUNK(0, 0);

        for (int kc = 0; kc < 16; kc++) {
            if (kc < 15) {
                FILL_CHUNK(kc + 1, (kc + 1) & 1);
                CP_WAIT(1);
            } else {
                CP_WAIT(0);
            }
            __syncthreads();

            const uint32_t* Ah = smem + (kc & 1) * BUF_U32;
            const uint32_t* Al = Ah + PLANE_U32;
            const uint32_t* Bs = Ah + 2 * PLANE_U32;

#pragma unroll
            for (int kb = 0; kb < 2; kb++) {
                const int ko = kb * 8;
                uint32_t bfr[4][2];
#pragma unroll
                for (int ntt = 0; ntt < 4; ntt++) {
                    int n = wn * 32 + ntt * 8 + g8;
                    bfr[ntt][0] = Bs[n * SPAD + ko + tig];
                    bfr[ntt][1] = Bs[n * SPAD + ko + tig + 4];
                }
#pragma unroll
                for (int mtt = 0; mtt < 4; mtt++) {
                    int r = wm * 64 + mtt * 16 + g8;
                    uint32_t ah[4], al[4];
                    ah[0] = Ah[r * SPAD + ko + tig];
                    ah[1] = Ah[(r + 8) * SPAD + ko + tig];
                    ah[2] = Ah[r * SPAD + ko + tig + 4];
                    ah[3] = Ah[(r + 8) * SPAD + ko + tig + 4];
                    al[0] = Al[r * SPAD + ko + tig];
                    al[1] = Al[(r + 8) * SPAD + ko + tig];
                    al[2] = Al[r * SPAD + ko + tig + 4];
                    al[3] = Al[(r + 8) * SPAD + ko + tig + 4];
#pragma unroll
                    for (int ntt = 0; ntt < 4; ntt++) mma_f16(acc[mtt][ntt], ah, bfr[ntt]);
#pragma unroll
                    for (int ntt = 0; ntt < 4; ntt++) mma_f16(acc[mtt][ntt], al, bfr[ntt]);
                }
            }
            __syncthreads();
        }
#undef FILL_CHUNK

        // ---- epilogue ----
        const float* Hin = Hf + (size_t)(t & 1) * NH;
        float* Hout = Hf + (size_t)((t + 1) & 1) * NH;
        uint32_t* pl_hi = (uint32_t*)Hpl + (size_t)((t + 1) & 1) * 2 * PL;
        uint32_t* pl_lo = pl_hi + PL;
        uint32_t* hr_hi = (uint32_t*)Hrpl;
        uint32_t* hr_lo = hr_hi + PL;
        uint32_t* ha_hi = (uint32_t*)HApl;
        uint32_t* ha_lo = ha_hi + PL;
        const float p = (type == 1) ? probs[t] : 0.f;
        const bool last_t = (type == 1) && (t == T_DIM - 1);

#pragma unroll
        for (int mtt = 0; mtt < 4; mtt++) {
#pragma unroll
            for (int i = 0; i < 2; i++) {
                int rl = wm * 64 + mtt * 16 + g8 + i * 8;
                int gr = row0 + rl;
                if (gr >= N_NODES) continue;
                float a0 = 0.f, a1 = 0.f, a2 = 0.f, a3 = 0.f;
                if (type != 2) {
                    a0 = aggS[rl * 4 + 0]; a1 = aggS[rl * 4 + 1];
                    a2 = aggS[rl * 4 + 2]; a3 = aggS[rl * 4 + 3];
                }
#pragma unroll
                for (int ntt = 0; ntt < 4; ntt++) {
                    const int cg0 = col0 + wn * 32 + ntt * 8 + tig * 2;
                    float vv[2];
#pragma unroll
                    for (int jj = 0; jj < 2; jj++) {
                        int cg = cg0 + jj;
                        float v = acc[mtt][ntt][i * 2 + jj] + beff[cg];
                        if (type != 2)
                            v += a0 * U[cg] + a1 * U[ustride + cg]
                               + a2 * U[2 * ustride + cg] + a3 * U[3 * ustride + cg];
                        vv[jj] = v;
                    }
                    if (type == 0) {
                        if (cg0 < 512) {
                            zb[(size_t)gr * C_DIM + cg0]     = 1.f / (1.f + expf(-vv[0]));
                            zb[(size_t)gr * C_DIM + cg0 + 1] = 1.f / (1.f + expf(-vv[1]));
                        } else {
                            size_t o = (size_t)gr * C_DIM + (cg0 - 512);
                            float hr0 = __ldcg(Hin + o)     * (1.f / (1.f + expf(-vv[0])));
                            float hr1 = __ldcg(Hin + o + 1) * (1.f / (1.f + expf(-vv[1])));
                            size_t pp = (size_t)gr * KPAIRS + ((cg0 - 512) >> 1);
                            split2_store_f16(hr0, hr1, &hr_hi[pp], &hr_lo[pp]);
                        }
                    } else if (type == 1) {
                        size_t o = (size_t)gr * C_DIM + cg0;
                        float z0 = __ldcg(zb + o), z1 = __ldcg(zb + o + 1);
                        float hn0 = z0 * __ldcg(Hin + o)     + (1.f - z0) * tanhf(vv[0]);
                        float hn1 = z1 * __ldcg(Hin + o + 1) + (1.f - z1) * tanhf(vv[1]);
                        Hout[o]     = hn0;
                        Hout[o + 1] = hn1;
                        size_t pp = (size_t)gr * KPAIRS + (cg0 >> 1);
                        split2_store_f16(hn0, hn1, &pl_hi[pp], &pl_lo[pp]);
                        float ha0 = __ldcg(Hacc + o)     + p * hn0;
                        float ha1 = __ldcg(Hacc + o + 1) + p * hn1;
                        Hacc[o]     = ha0;
                        Hacc[o + 1] = ha1;
                        if (last_t)
                            split2_store_f16(fmaxf(ha0, 0.f), fmaxf(ha1, 0.f),
                                             &ha_hi[pp], &ha_lo[pp]);
                    } else {
                        h1[(size_t)gr * HID_DIM + cg0]     = fmaxf(vv[0], 0.f);
                        h1[(size_t)gr * HID_DIM + cg0 + 1] = fmaxf(vv[1], 0.f);
                    }
                }
            }
        }

        // ---- publish ----
        __threadfence();
        __syncthreads();
        if (tid == 0) {
            if (type == 0)      atomicAdd(&zrC[t * MTILES + mt], 1);
            else if (type == 1) atomicAdd(&hC[t * MTILES + mt], 1);
        }
        __syncthreads();
    }
}

// out[i,j] = h1[i,:] @ W2[:,j] + b2[j]
__global__ void head2(const float* __restrict__ h1, const float* __restrict__ W2,
                      const float* __restrict__ b2, float* __restrict__ out) {
    int idx = blockIdx.x * blockDim.x + threadIdx.x;
    if (idx >= N_NODES * OUT_DIM) return;
    int i = idx / OUT_DIM;
    int j = idx % OUT_DIM;
    float s = b2[j];
    const float* hr = h1 + (size_t)i * HID_DIM;
    for (int k = 0; k < HID_DIM; k++) s += hr[k] * W2[k * OUT_DIM + j];
    out[idx] = s;
}
__global__ void copy_hidden(const float* __restrict__ Hacc, float* __restrict__ out) {
    int idx = blockIdx.x * blockDim.x + threadIdx.x;
    if (idx >= N_NODES * C_DIM) return;
    out[idx] = Hacc[idx];
}

// ---------------- host launcher ----------------
extern "C" void kernel_launch(void* const* d_in, const int* in_sizes, int n_in,
                              void* d_out, int out_size) {
    const float* x   = (const float*)d_in[0];
    const int*   ei  = (const int*)d_in[1];
    const float* ea  = (const float*)d_in[2];
    const float* att = (const float*)d_in[3];
    const float* Wg[3] = {(const float*)d_in[4],  (const float*)d_in[8],  (const float*)d_in[12]};
    const float* bg[3] = {(const float*)d_in[5],  (const float*)d_in[9],  (const float*)d_in[13]};
    const float* Wl[3] = {(const float*)d_in[6],  (const float*)d_in[10], (const float*)d_in[14]};
    const float* bl[3] = {(const float*)d_in[7],  (const float*)d_in[11], (const float*)d_in[15]};
    const float* W1 = (const float*)d_in[16];
    const float* b1 = (const float*)d_in[17];
    const float* W2 = (const float*)d_in[18];
    const float* b2 = (const float*)d_in[19];
    float* out = (float*)d_out;

    float *deg, *dinv, *agg, *U, *beff, *Uzr, *beffzr, *probs, *Hbase, *zb, *Hacc, *h1;
    uint32_t *Bt, *Hpl, *Hrpl, *HApl;
    int *cursor, *zrC, *hC;
    cudaGetSymbolAddress((void**)&deg,    g_deg);
    cudaGetSymbolAddress((void**)&dinv,   g_dinv);
    cudaGetSymbolAddress((void**)&agg,    g_agg);
    cudaGetSymbolAddress((void**)&U,      g_U);
    cudaGetSymbolAddress((void**)&beff,   g_beff);
    cudaGetSymbolAddress((void**)&Uzr,    g_Uzr);
    cudaGetSymbolAddress((void**)&beffzr, g_beffzr);
    cudaGetSymbolAddress((void**)&probs,  g_probs);
    cudaGetSymbolAddress((void**)&Hbase,  g_H);
    cudaGetSymbolAddress((void**)&zb,     g_z);
    cudaGetSymbolAddress((void**)&Hacc,   g_Hacc);
    cudaGetSymbolAddress((void**)&h1,     g_h1);
    cudaGetSymbolAddress((void**)&Bt,     g_Bt);
    cudaGetSymbolAddress((void**)&Hpl,    g_Hpl);
    cudaGetSymbolAddress((void**)&Hrpl,   g_Hrpl);
    cudaGetSymbolAddress((void**)&HApl,   g_HApl);
    cudaGetSymbolAddress((void**)&cursor, g_cursor);
    cudaGetSymbolAddress((void**)&zrC,    g_zrC);
    cudaGetSymbolAddress((void**)&hC,     g_hC);
    const size_t PL = (size_t)N_NODES * KPAIRS;

    cudaFuncSetAttribute(megakernel, cudaFuncAttributeMaxDynamicSharedMemorySize, SMEM_BYTES);

    // setup
    init_state<<<(N_NODES * C_DIM + 255) / 256, 256>>>(Hbase, Hacc, deg,
                                                       Hpl, Hpl + PL, zrC, hC, cursor);
    deg_scatter<<<(N_EDGES + 255) / 256, 256>>>(ei, ea, deg);
    compute_dinv<<<(N_NODES + 255) / 256, 256>>>(deg, dinv);
    agg_init<<<(N_NODES * FT + 255) / 256, 256>>>(x, dinv, agg);
    {
        long long tot = (long long)N_EDGES * FT;
        agg_scatter<<<(unsigned)((tot + 255) / 256), 256>>>(x, ei, ea, dinv, agg);
    }
    softmax12<<<1, 32>>>(att, probs);
    compute_U<<<(3 * F_DIM * C_DIM + 255) / 256, 256>>>(Wg[0], Wg[1], Wg[2], Wl[0], Wl[1], Wl[2], U);
    compute_beff<<<(3 * C_DIM + 255) / 256, 256>>>(bg[0], bg[1], bg[2], Wl[0], Wl[1], Wl[2],
                                                   bl[0], bl[1], bl[2], beff);
    pack_zr<<<(F_DIM * 1024 + 255) / 256, 256>>>(U, beff, Uzr, beffzr);
    transpose_B_f16<<<(BT_PAIRS + 255) / 256, 256>>>(Wl[0], Wl[1], Wl[2], W1, Bt);

    // one persistent launch: all 12 timesteps (zr + h) + head1
    megakernel<<<GRID_PERSIST, 256, SMEM_BYTES>>>(
        Hpl, Hrpl, HApl, Bt,
        Hbase, zb, Hacc, h1,
        agg, Uzr, U, beffzr, beff, b1, probs,
        cursor, zrC, hC);

    head2<<<(N_NODES * OUT_DIM + 255) / 256, 256>>>(h1, W2, b2, out);
    copy_hidden<<<(N_NODES * C_DIM + 255) / 256, 256>>>(Hacc, out + (size_t)N_NODES * OUT_DIM);
}

// round 17
// speedup vs baseline: 2.0608x; 1.2613x over previous
#include <cuda_runtime.h>
#include <cuda_fp16.h>
#include <cstdint>
#include <math.h>

#define N_NODES 10000
#define N_EDGES 160000
#define F_DIM 4
#define T_DIM 12
#define C_DIM 512
#define HID_DIM 256
#define OUT_DIM 12
#define FT (F_DIM * T_DIM)
#define KPAIRS 256
#define MTILES 79
#define TILES_ZR (MTILES * 8)            // 632
#define TILES_H  (MTILES * 4)            // 316
#define TILES_PER_T (TILES_ZR + TILES_H) // 948
#define TILES_HEAD (MTILES * 2)          // 158
#define TOTAL_TILES (T_DIM * TILES_PER_T + TILES_HEAD)  // 11534
#define GRID_PERSIST 296

// ---------------- scratch ----------------
__device__ float g_deg[N_NODES];
__device__ float g_dinv[N_NODES];
__device__ float g_agg[(size_t)N_NODES * FT];
__device__ float g_U[3 * F_DIM * C_DIM];
__device__ float g_beff[3 * C_DIM];
__device__ float g_Uzr[F_DIM * 2 * C_DIM];
__device__ float g_beffzr[2 * C_DIM];
__device__ float g_probs[T_DIM];
__device__ float g_H[2][(size_t)N_NODES * C_DIM];
__device__ float g_z[(size_t)N_NODES * C_DIM];
__device__ float g_Hacc[(size_t)N_NODES * C_DIM];
__device__ float g_h1[(size_t)N_NODES * HID_DIM];
// fp16 packed planes (A operands), single precision plane each
__device__ uint32_t g_Hpl[2][(size_t)N_NODES * KPAIRS];   // [buf]
__device__ uint32_t g_Hrpl[(size_t)N_NODES * KPAIRS];
__device__ uint32_t g_HApl[(size_t)N_NODES * KPAIRS];
// transposed fp16 pair-packed weights (single plane)
#define BT_ZR_OFF 0
#define BT_H_OFF  (1024 * 256)
#define BT_1_OFF  (1024 * 256 + 512 * 256)
#define BT_PAIRS  ((1024 + 512 + 256) * 256)
__device__ uint32_t g_Bt[BT_PAIRS];
// scheduler state
__device__ int g_cursor;
__device__ int g_zrC[T_DIM * MTILES];
__device__ int g_hC[T_DIM * MTILES];

// ---------------- helpers ----------------
__device__ __forceinline__ uint32_t pack_f16x2(float a, float b) {
    __half2 h = __floats2half2_rn(a, b);
    return *(uint32_t*)&h;
}
__device__ __forceinline__ void mma_f16(float* c, const uint32_t* a, const uint32_t* b) {
    asm volatile(
        "mma.sync.aligned.m16n8k16.row.col.f32.f16.f16.f32 "
        "{%0,%1,%2,%3}, {%4,%5,%6,%7}, {%8,%9}, {%0,%1,%2,%3};"
        : "+f"(c[0]), "+f"(c[1]), "+f"(c[2]), "+f"(c[3])
        : "r"(a[0]), "r"(a[1]), "r"(a[2]), "r"(a[3]), "r"(b[0]), "r"(b[1]));
}
#define CP_ASYNC16(dst, src, sz) \
    asm volatile("cp.async.cg.shared.global [%0], [%1], 16, %2;" \
        :: "r"(dst), "l"(src), "r"(sz) : "memory")
#define CP_COMMIT() asm volatile("cp.async.commit_group;" ::: "memory")
#define CP_WAIT(n)  asm volatile("cp.async.wait_group %0;" :: "n"(n) : "memory")

// ---------------- small setup kernels ----------------
__global__ void init_state(float* H0, float* Hacc, float* deg,
                           uint32_t* Hpl0, int* zrC, int* hC, int* cursor) {
    int idx = blockIdx.x * blockDim.x + threadIdx.x;
    if (idx < N_NODES * C_DIM) { H0[idx] = 0.f; Hacc[idx] = 0.f; }
    if (idx < N_NODES * KPAIRS) Hpl0[idx] = 0u;
    if (idx < N_NODES) deg[idx] = 1.f;
    if (idx < T_DIM * MTILES) { zrC[idx] = 0; hC[idx] = 0; }
    if (idx == 0) *cursor = 0;
}
__global__ void deg_scatter(const int* __restrict__ ei, const float* __restrict__ ea,
                            float* __restrict__ deg) {
    int e = blockIdx.x * blockDim.x + threadIdx.x;
    if (e >= N_EDGES) return;
    atomicAdd(&deg[ei[N_EDGES + e]], ea[e]);
}
__global__ void compute_dinv(const float* __restrict__ deg, float* __restrict__ dinv) {
    int i = blockIdx.x * blockDim.x + threadIdx.x;
    if (i >= N_NODES) return;
    dinv[i] = rsqrtf(fmaxf(deg[i], 1e-12f));
}
__global__ void agg_init(const float* __restrict__ x, const float* __restrict__ dinv,
                         float* __restrict__ agg) {
    int idx = blockIdx.x * blockDim.x + threadIdx.x;
    if (idx >= N_NODES * FT) return;
    int i = idx / FT;
    float d = dinv[i];
    agg[idx] = d * d * x[idx];
}
__global__ void agg_scatter(const float* __restrict__ x, const int* __restrict__ ei,
                            const float* __restrict__ ea, const float* __restrict__ dinv,
                            float* __restrict__ agg) {
    long long idx = (long long)blockIdx.x * blockDim.x + threadIdx.x;
    if (idx >= (long long)N_EDGES * FT) return;
    int e = (int)(idx / FT);
    int k = (int)(idx % FT);
    int s = ei[e];
    int d = ei[N_EDGES + e];
    float coef = dinv[s] * ea[e] * dinv[d];
    atomicAdd(&agg[(size_t)d * FT + k], coef * x[(size_t)s * FT + k]);
}
__global__ void softmax12(const float* __restrict__ att, float* __restrict__ probs) {
    if (threadIdx.x == 0) {
        float m = -1e30f;
        for (int i = 0; i < T_DIM; i++) m = fmaxf(m, att[i]);
        float e[T_DIM]; float s = 0.f;
        for (int i = 0; i < T_DIM; i++) { e[i] = expf(att[i] - m); s += e[i]; }
        float inv = 1.f / s;
        for (int i = 0; i < T_DIM; i++) probs[i] = e[i] * inv;
    }
}
__global__ void compute_U(const float* Wzg, const float* Wrg, const float* Whg,
                          const float* Wzl, const float* Wrl, const float* Whl,
                          float* U) {
    int idx = blockIdx.x * blockDim.x + threadIdx.x;
    if (idx >= 3 * F_DIM * C_DIM) return;
    int g = idx / (F_DIM * C_DIM);
    int rem = idx % (F_DIM * C_DIM);
    int f = rem / C_DIM;
    int c = rem % C_DIM;
    const float* Wg = (g == 0) ? Wzg : (g == 1) ? Wrg : Whg;
    const float* Wl = (g == 0) ? Wzl : (g == 1) ? Wrl : Whl;
    float s = 0.f;
    for (int k = 0; k < C_DIM; k++) s += Wg[f * C_DIM + k] * Wl[(size_t)k * C_DIM + c];
    U[idx] = s;
}
__global__ void compute_beff(const float* bzg, const float* brg, const float* bhg,
                             const float* Wzl, const float* Wrl, const float* Whl,
                             const float* bzl, const float* brl, const float* bhl,
                             float* beff) {
    int idx = blockIdx.x * blockDim.x + threadIdx.x;
    if (idx >= 3 * C_DIM) return;
    int g = idx / C_DIM;
    int c = idx % C_DIM;
    const float* bg = (g == 0) ? bzg : (g == 1) ? brg : bhg;
    const float* Wl = (g == 0) ? Wzl : (g == 1) ? Wrl : Whl;
    const float* bl = (g == 0) ? bzl : (g == 1) ? brl : bhl;
    float s = bl[c];
    for (int k = 0; k < C_DIM; k++) s += bg[k] * Wl[(size_t)k * C_DIM + c];
    beff[idx] = s;
}
__global__ void pack_zr(const float* __restrict__ U, const float* __restrict__ beff,
                        float* __restrict__ Uzr, float* __restrict__ beffzr) {
    int idx = blockIdx.x * blockDim.x + threadIdx.x;
    if (idx < F_DIM * 1024) {
        int f = idx >> 10;
        int c = idx & 1023;
        int gt = (c >> 9);
        Uzr[idx] = U[gt * (F_DIM * C_DIM) + f * C_DIM + (c & 511)];
    }
    if (idx < 1024) {
        int gt = idx >> 9;
        beffzr[idx] = beff[gt * C_DIM + (idx & 511)];
    }
}
// transposed fp16 pair-packed weight plane
__global__ void transpose_B_f16(const float* Wzl, const float* Wrl, const float* Whl,
                                const float* W1, uint32_t* __restrict__ Bt) {
    int idx = blockIdx.x * blockDim.x + threadIdx.x;
    if (idx >= BT_PAIRS) return;
    const int ZR = 1024 * 256, HH = 512 * 256;
    float v0, v1;
    if (idx < ZR) {
        int n = idx >> 8, pk = idx & 255;
        int k0 = pk * 2;
        if (n < 512) {
            v0 = Wzl[(size_t)(C_DIM + k0) * C_DIM + n];
            v1 = Wzl[(size_t)(C_DIM + k0 + 1) * C_DIM + n];
        } else {
            v0 = Wrl[(size_t)(C_DIM + k0) * C_DIM + (n - 512)];
            v1 = Wrl[(size_t)(C_DIM + k0 + 1) * C_DIM + (n - 512)];
        }
    } else if (idx < ZR + HH) {
        int r = idx - ZR;
        int n = r >> 8, pk = r & 255;
        int k0 = pk * 2;
        v0 = Whl[(size_t)(C_DIM + k0) * C_DIM + n];
        v1 = Whl[(size_t)(C_DIM + k0 + 1) * C_DIM + n];
    } else {
        int r = idx - ZR - HH;
        int n = r >> 8, pk = r & 255;
        int k0 = pk * 2;
        v0 = W1[(size_t)k0 * HID_DIM + n];
        v1 = W1[(size_t)(k0 + 1) * HID_DIM + n];
    }
    Bt[idx] = pack_f16x2(v0, v1);
}

// ---------------- persistent megakernel (single fp16 both operands) ----------------
#define BMT 128
#define SPAD 20
#define PLANE_U32 (BMT * SPAD)       // 2560
#define BUF_U32   (2 * PLANE_U32)    // 5120 (A, B)
#define SMEM_U32  (2 * BUF_U32 + BMT * F_DIM)
#define SMEM_BYTES (SMEM_U32 * 4)    // 43008

__global__ __launch_bounds__(256, 2) void megakernel(
    const uint32_t* __restrict__ Hpl,    // [2 bufs][PL]
    const uint32_t* __restrict__ Hrpl,   // [PL]
    const uint32_t* __restrict__ HApl,   // [PL]
    const uint32_t* __restrict__ Bt,
    float* __restrict__ Hf,
    float* __restrict__ zb,
    float* __restrict__ Hacc,
    float* __restrict__ h1,
    const float* __restrict__ agg,
    const float* __restrict__ Uzr, const float* __restrict__ Ug,
    const float* __restrict__ beffzr, const float* __restrict__ beffg,
    const float* __restrict__ b1,
    const float* __restrict__ probs,
    int* __restrict__ cursor, int* __restrict__ zrC, int* __restrict__ hC)
{
    extern __shared__ uint32_t smem[];
    float* aggS = (float*)(smem + 2 * BUF_U32);
    __shared__ int s_id;

    const int tid = threadIdx.x;
    const int wid = tid >> 5;
    const int lane = tid & 31;
    const int g8 = lane >> 2;
    const int tig = lane & 3;
    const int wm = wid >> 2;
    const int wn = wid & 3;
    const int f_r = tid >> 1;
    const int f_q = (tid & 1) * 2;
    const size_t PL = (size_t)N_NODES * KPAIRS;
    const size_t NH = (size_t)N_NODES * C_DIM;
    const uint32_t smem_fill0 =
        (uint32_t)__cvta_generic_to_shared(smem + f_r * SPAD + f_q * 4);

    for (;;) {
        if (tid == 0) s_id = atomicAdd(cursor, 1);
        __syncthreads();
        const int id = s_id;
        if (id >= TOTAL_TILES) break;

        // ---- decode tile ----
        int type, t, mt, nt;
        if (id < T_DIM * TILES_PER_T) {
            t = id / TILES_PER_T;
            int r = id % TILES_PER_T;
            if (r < TILES_ZR) { type = 0; mt = r >> 3; nt = r & 7; }
            else { int r2 = r - TILES_ZR; type = 1; mt = r2 >> 2; nt = r2 & 3; }
        } else {
            int r = id - T_DIM * TILES_PER_T;
            type = 2; t = 0; mt = r >> 1; nt = r & 1;
        }
        const int row0 = mt * BMT;
        const int col0 = nt * 128;

        // ---- wait deps ----
        if (tid == 0) {
            if (type == 0) {
                if (t > 0) { int* c = &hC[(t - 1) * MTILES + mt];
                    while (atomicAdd(c, 0) < 4) __nanosleep(64); }
            } else if (type == 1) {
                int* c = &zrC[t * MTILES + mt];
                while (atomicAdd(c, 0) < 8) __nanosleep(64);
            } else {
                int* c = &hC[(T_DIM - 1) * MTILES + mt];
                while (atomicAdd(c, 0) < 4) __nanosleep(64);
            }
        }
        __syncthreads();

        // ---- per-tile operand pointers ----
        const uint32_t *Ag, *Bg;
        const float *U, *beff;
        int ustride = 512;
        if (type == 0) {
            Ag = Hpl + (size_t)(t & 1) * PL;
            Bg = Bt + BT_ZR_OFF;
            U = Uzr; beff = beffzr; ustride = 1024;
        } else if (type == 1) {
            Ag = Hrpl;
            Bg = Bt + BT_H_OFF;
            U = Ug + 2 * F_DIM * C_DIM; beff = beffg + 2 * C_DIM;
        } else {
            Ag = HApl;
            Bg = Bt + BT_1_OFF;
            U = Ug; beff = b1;
        }

        if (type != 2) {
            for (int i = tid; i < BMT * F_DIM; i += 256) {
                int r = i >> 2, f = i & 3;
                aggS[i] = (row0 + r < N_NODES)
                        ? __ldcg(agg + (size_t)(row0 + r) * FT + f * T_DIM + t) : 0.f;
            }
        }

        const int a_gr = row0 + f_r;
        const uint32_t a_sz = (a_gr < N_NODES) ? 16u : 0u;
        const uint4* Ag_p = (const uint4*)Ag + (size_t)a_gr * 64 + f_q;
        const uint4* Bg_p = (const uint4*)Bg + (size_t)(col0 + f_r) * 64 + f_q;

#define FILL_CHUNK(kc_, buf_) do {                                          \
        int _k4 = (kc_) * 4;                                                \
        uint32_t _d = smem_fill0 + (buf_) * (BUF_U32 * 4);                  \
        CP_ASYNC16(_d,                    Ag_p + _k4,     a_sz);            \
        CP_ASYNC16(_d + 16,               Ag_p + _k4 + 1, a_sz);            \
        CP_ASYNC16(_d + PLANE_U32*4,      Bg_p + _k4,     16u);             \
        CP_ASYNC16(_d + PLANE_U32*4 + 16, Bg_p + _k4 + 1, 16u);             \
        CP_COMMIT();                                                        \
    } while (0)

        float acc[4][4][4];
#pragma unroll
        for (int a = 0; a < 4; a++)
#pragma unroll
            for (int b = 0; b < 4; b++)
#pragma unroll
                for (int c = 0; c < 4; c++) acc[a][b][c] = 0.f;

        FILL_CHUNK(0, 0);

        for (int kc = 0; kc < 16; kc++) {
            if (kc < 15) {
                FILL_CHUNK(kc + 1, (kc + 1) & 1);
                CP_WAIT(1);
            } else {
                CP_WAIT(0);
            }
            __syncthreads();

            const uint32_t* Ah = smem + (kc & 1) * BUF_U32;
            const uint32_t* Bs = Ah + PLANE_U32;

#pragma unroll
            for (int kb = 0; kb < 2; kb++) {
                const int ko = kb * 8;
                uint32_t bfr[4][2];
#pragma unroll
                for (int ntt = 0; ntt < 4; ntt++) {
                    int n = wn * 32 + ntt * 8 + g8;
                    bfr[ntt][0] = Bs[n * SPAD + ko + tig];
                    bfr[ntt][1] = Bs[n * SPAD + ko + tig + 4];
                }
#pragma unroll
                for (int mtt = 0; mtt < 4; mtt++) {
                    int r = wm * 64 + mtt * 16 + g8;
                    uint32_t ah[4];
                    ah[0] = Ah[r * SPAD + ko + tig];
                    ah[1] = Ah[(r + 8) * SPAD + ko + tig];
                    ah[2] = Ah[r * SPAD + ko + tig + 4];
                    ah[3] = Ah[(r + 8) * SPAD + ko + tig + 4];
#pragma unroll
                    for (int ntt = 0; ntt < 4; ntt++) mma_f16(acc[mtt][ntt], ah, bfr[ntt]);
                }
            }
            __syncthreads();
        }
#undef FILL_CHUNK

        // ---- epilogue ----
        const float* Hin = Hf + (size_t)(t & 1) * NH;
        float* Hout = Hf + (size_t)((t + 1) & 1) * NH;
        uint32_t* pl = (uint32_t*)Hpl + (size_t)((t + 1) & 1) * PL;
        uint32_t* hrp = (uint32_t*)Hrpl;
        uint32_t* hap = (uint32_t*)HApl;
        const float p = (type == 1) ? probs[t] : 0.f;
        const bool last_t = (type == 1) && (t == T_DIM - 1);

#pragma unroll
        for (int mtt = 0; mtt < 4; mtt++) {
#pragma unroll
            for (int i = 0; i < 2; i++) {
                int rl = wm * 64 + mtt * 16 + g8 + i * 8;
                int gr = row0 + rl;
                if (gr >= N_NODES) continue;
                float a0 = 0.f, a1 = 0.f, a2 = 0.f, a3 = 0.f;
                if (type != 2) {
                    a0 = aggS[rl * 4 + 0]; a1 = aggS[rl * 4 + 1];
                    a2 = aggS[rl * 4 + 2]; a3 = aggS[rl * 4 + 3];
                }
#pragma unroll
                for (int ntt = 0; ntt < 4; ntt++) {
                    const int cg0 = col0 + wn * 32 + ntt * 8 + tig * 2;
                    float vv[2];
#pragma unroll
                    for (int jj = 0; jj < 2; jj++) {
                        int cg = cg0 + jj;
                        float v = acc[mtt][ntt][i * 2 + jj] + beff[cg];
                        if (type != 2)
                            v += a0 * U[cg] + a1 * U[ustride + cg]
                               + a2 * U[2 * ustride + cg] + a3 * U[3 * ustride + cg];
                        vv[jj] = v;
                    }
                    if (type == 0) {
                        if (cg0 < 512) {
                            zb[(size_t)gr * C_DIM + cg0]     = 1.f / (1.f + expf(-vv[0]));
                            zb[(size_t)gr * C_DIM + cg0 + 1] = 1.f / (1.f + expf(-vv[1]));
                        } else {
                            size_t o = (size_t)gr * C_DIM + (cg0 - 512);
                            float hr0 = __ldcg(Hin + o)     * (1.f / (1.f + expf(-vv[0])));
                            float hr1 = __ldcg(Hin + o + 1) * (1.f / (1.f + expf(-vv[1])));
                            hrp[(size_t)gr * KPAIRS + ((cg0 - 512) >> 1)] = pack_f16x2(hr0, hr1);
                        }
                    } else if (type == 1) {
                        size_t o = (size_t)gr * C_DIM + cg0;
                        float z0 = __ldcg(zb + o), z1 = __ldcg(zb + o + 1);
                        float hn0 = z0 * __ldcg(Hin + o)     + (1.f - z0) * tanhf(vv[0]);
                        float hn1 = z1 * __ldcg(Hin + o + 1) + (1.f - z1) * tanhf(vv[1]);
                        Hout[o]     = hn0;
                        Hout[o + 1] = hn1;
                        size_t pp = (size_t)gr * KPAIRS + (cg0 >> 1);
                        pl[pp] = pack_f16x2(hn0, hn1);
                        float ha0 = __ldcg(Hacc + o)     + p * hn0;
                        float ha1 = __ldcg(Hacc + o + 1) + p * hn1;
                        Hacc[o]     = ha0;
                        Hacc[o + 1] = ha1;
                        if (last_t)
                            hap[pp] = pack_f16x2(fmaxf(ha0, 0.f), fmaxf(ha1, 0.f));
                    } else {
                        h1[(size_t)gr * HID_DIM + cg0]     = fmaxf(vv[0], 0.f);
                        h1[(size_t)gr * HID_DIM + cg0 + 1] = fmaxf(vv[1], 0.f);
                    }
                }
            }
        }

        // ---- publish ----
        __threadfence();
        __syncthreads();
        if (tid == 0) {
            if (type == 0)      atomicAdd(&zrC[t * MTILES + mt], 1);
            else if (type == 1) atomicAdd(&hC[t * MTILES + mt], 1);
        }
        __syncthreads();
    }
}

// out[i,j] = h1[i,:] @ W2[:,j] + b2[j]
__global__ void head2(const float* __restrict__ h1, const float* __restrict__ W2,
                      const float* __restrict__ b2, float* __restrict__ out) {
    int idx = blockIdx.x * blockDim.x + threadIdx.x;
    if (idx >= N_NODES * OUT_DIM) return;
    int i = idx / OUT_DIM;
    int j = idx % OUT_DIM;
    float s = b2[j];
    const float* hr = h1 + (size_t)i * HID_DIM;
    for (int k = 0; k < HID_DIM; k++) s += hr[k] * W2[k * OUT_DIM + j];
    out[idx] = s;
}
__global__ void copy_hidden(const float* __restrict__ Hacc, float* __restrict__ out) {
    int idx = blockIdx.x * blockDim.x + threadIdx.x;
    if (idx >= N_NODES * C_DIM) return;
    out[idx] = Hacc[idx];
}

// ---------------- host launcher ----------------
extern "C" void kernel_launch(void* const* d_in, const int* in_sizes, int n_in,
                              void* d_out, int out_size) {
    const float* x   = (const float*)d_in[0];
    const int*   ei  = (const int*)d_in[1];
    const float* ea  = (const float*)d_in[2];
    const float* att = (const float*)d_in[3];
    const float* Wg[3] = {(const float*)d_in[4],  (const float*)d_in[8],  (const float*)d_in[12]};
    const float* bg[3] = {(const float*)d_in[5],  (const float*)d_in[9],  (const float*)d_in[13]};
    const float* Wl[3] = {(const float*)d_in[6],  (const float*)d_in[10], (const float*)d_in[14]};
    const float* bl[3] = {(const float*)d_in[7],  (const float*)d_in[11], (const float*)d_in[15]};
    const float* W1 = (const float*)d_in[16];
    const float* b1 = (const float*)d_in[17];
    const float* W2 = (const float*)d_in[18];
    const float* b2 = (const float*)d_in[19];
    float* out = (float*)d_out;

    float *deg, *dinv, *agg, *U, *beff, *Uzr, *beffzr, *probs, *Hbase, *zb, *Hacc, *h1;
    uint32_t *Bt, *Hpl, *Hrpl, *HApl;
    int *cursor, *zrC, *hC;
    cudaGetSymbolAddress((void**)&deg,    g_deg);
    cudaGetSymbolAddress((void**)&dinv,   g_dinv);
    cudaGetSymbolAddress((void**)&agg,    g_agg);
    cudaGetSymbolAddress((void**)&U,      g_U);
    cudaGetSymbolAddress((void**)&beff,   g_beff);
    cudaGetSymbolAddress((void**)&Uzr,    g_Uzr);
    cudaGetSymbolAddress((void**)&beffzr, g_beffzr);
    cudaGetSymbolAddress((void**)&probs,  g_probs);
    cudaGetSymbolAddress((void**)&Hbase,  g_H);
    cudaGetSymbolAddress((void**)&zb,     g_z);
    cudaGetSymbolAddress((void**)&Hacc,   g_Hacc);
    cudaGetSymbolAddress((void**)&h1,     g_h1);
    cudaGetSymbolAddress((void**)&Bt,     g_Bt);
    cudaGetSymbolAddress((void**)&Hpl,    g_Hpl);
    cudaGetSymbolAddress((void**)&Hrpl,   g_Hrpl);
    cudaGetSymbolAddress((void**)&HApl,   g_HApl);
    cudaGetSymbolAddress((void**)&cursor, g_cursor);
    cudaGetSymbolAddress((void**)&zrC,    g_zrC);
    cudaGetSymbolAddress((void**)&hC,     g_hC);

    cudaFuncSetAttribute(megakernel, cudaFuncAttributeMaxDynamicSharedMemorySize, SMEM_BYTES);

    // setup
    init_state<<<(N_NODES * C_DIM + 255) / 256, 256>>>(Hbase, Hacc, deg, Hpl, zrC, hC, cursor);
    deg_scatter<<<(N_EDGES + 255) / 256, 256>>>(ei, ea, deg);
    compute_dinv<<<(N_NODES + 255) / 256, 256>>>(deg, dinv);
    agg_init<<<(N_NODES * FT + 255) / 256, 256>>>(x, dinv, agg);
    {
        long long tot = (long long)N_EDGES * FT;
        agg_scatter<<<(unsigned)((tot + 255) / 256), 256>>>(x, ei, ea, dinv, agg);
    }
    softmax12<<<1, 32>>>(att, probs);
    compute_U<<<(3 * F_DIM * C_DIM + 255) / 256, 256>>>(Wg[0], Wg[1], Wg[2], Wl[0], Wl[1], Wl[2], U);
    compute_beff<<<(3 * C_DIM + 255) / 256, 256>>>(bg[0], bg[1], bg[2], Wl[0], Wl[1], Wl[2],
                                                   bl[0], bl[1], bl[2], beff);
    pack_zr<<<(F_DIM * 1024 + 255) / 256, 256>>>(U, beff, Uzr, beffzr);
    transpose_B_f16<<<(BT_PAIRS + 255) / 256, 256>>>(Wl[0], Wl[1], Wl[2], W1, Bt);

    // one persistent launch: all 12 timesteps (zr + h) + head1
    megakernel<<<GRID_PERSIST, 256, SMEM_BYTES>>>(
        Hpl, Hrpl, HApl, Bt,
        Hbase, zb, Hacc, h1,
        agg, Uzr, U, beffzr, beff, b1, probs,
        cursor, zrC, hC);

    head2<<<(N_NODES * OUT_DIM + 255) / 256, 256>>>(h1, W2, b2, out);
    copy_hidden<<<(N_NODES * C_DIM + 255) / 256, 256>>>(Hacc, out + (size_t)N_NODES * OUT_DIM);
}